// round 12
// baseline (speedup 1.0000x reference)
#include <cuda_runtime.h>
#include <cuda_fp16.h>
#include <cstdint>
#include <math.h>

#define BB   32
#define SS   64
#define TT   64
#define EE   256
#define HH   512
#define DD   512
#define KKQ  64
#define VOC  32000
#define G3   1536
#define MROWS (BB*(TT-1))   // 2016

#define NF_EMB   (BB*SS*EE)
#define NF_GI    (BB*SS*G3)
#define NF_WR    (BB*SS*2*HH)
#define NF_HENC  (2*BB*2*HH)
#define NF_K     (BB*SS*KKQ)
#define NF_V     (BB*SS*DD)
#define NF_DEMB  (BB*(TT-1)*EE)
#define NF_GID   (BB*(TT-1)*G3)
#define NF_HDEC  (BB*DD)
#define NF_HID   (BB*(TT-1)*DD)
#define NF_WHTE  (2*512*1536)
#define NF_WHTD  (512*1536)
#define NF_HGRU  (BB*DD)

#define NF_TOTAL (NF_EMB + 2*NF_GI + NF_WR + NF_HENC + NF_K + NF_V + NF_DEMB + NF_GID + \
                  NF_HDEC + NF_HID + NF_WHTE + NF_WHTD + NF_HGRU)

__device__ float g_scr[NF_TOTAL];
__device__ __half g_xh[MROWS * DD];
__device__ __half g_w2h[VOC * DD];
__device__ unsigned g_bars[8];   // 0..3 enc (dir,bg) groups; 4..7 dec chunks

__device__ __forceinline__ float sigm(float x) { return 1.0f / (1.0f + expf(-x)); }
__device__ __forceinline__ float gelu_f(float x) { return 0.5f * x * (1.0f + erff(x * 0.7071067811865475f)); }

__device__ __forceinline__ float ldcg1(const float* p) {
    float v; asm volatile("ld.global.cg.f32 %0, [%1];" : "=f"(v) : "l"(p)); return v;
}
__device__ __forceinline__ float4 ldcg4(const float* p) {
    float4 v;
    asm volatile("ld.global.cg.v4.f32 {%0,%1,%2,%3}, [%4];"
                 : "=f"(v.x), "=f"(v.y), "=f"(v.z), "=f"(v.w) : "l"(p));
    return v;
}

__device__ __forceinline__ void ffma2(unsigned long long& d,
                                      unsigned long long a, unsigned long long b) {
    asm("fma.rn.f32x2 %0, %1, %2, %0;" : "+l"(d) : "l"(a), "l"(b));
}
__device__ __forceinline__ float hsum2(unsigned long long v) {
    float lo = __uint_as_float((unsigned)(v & 0xffffffffull));
    float hi = __uint_as_float((unsigned)(v >> 32));
    return lo + hi;
}

__device__ __forceinline__ void gsync(unsigned* bar, unsigned& epoch, unsigned nb) {
    __syncthreads();
    if (threadIdx.x == 0) {
        epoch += nb;
        __threadfence();
        atomicAdd(bar, 1u);
        while (*(volatile unsigned*)bar < epoch) __nanosleep(32);
        __threadfence();
    }
    __syncthreads();
}

// ---------------- init ----------------
__global__ void init_zero(float* __restrict__ out, float* __restrict__ henc) {
    int i = blockIdx.x * blockDim.x + threadIdx.x;
    if (i < 8) g_bars[i] = 0;
    if (i < BB * VOC) {
        int b = i / VOC;
        out[(size_t)b * TT * VOC + (i % VOC)] = 0.0f;
    }
    if (i < NF_HENC) henc[i] = 0.0f;
}

// ---------------- embedding gathers ----------------
__global__ void gather_src(const int* __restrict__ src, const float* __restrict__ tab,
                           float* __restrict__ emb) {
    int i = blockIdx.x * blockDim.x + threadIdx.x;
    if (i >= BB * SS * (EE / 4)) return;
    int row = i / (EE / 4);
    int c   = i % (EE / 4);
    ((float4*)emb)[row * (EE / 4) + c] =
        ((const float4*)tab)[(size_t)src[row] * (EE / 4) + c];
}

__global__ void gather_trg(const int* __restrict__ trg, const float* __restrict__ tab,
                           float* __restrict__ demb) {
    int i = blockIdx.x * blockDim.x + threadIdx.x;
    if (i >= BB * (TT - 1) * (EE / 4)) return;
    int m = i / (EE / 4);
    int c = i % (EE / 4);
    int t = m / BB, b = m % BB;
    int tok = trg[b * TT + t];
    ((float4*)demb)[m * (EE / 4) + c] =
        ((const float4*)tab)[(size_t)tok * (EE / 4) + c];
}

// ---------------- transpose-pack recurrent weights: [dir][j][gate][k] ----------------
__global__ void pack_whT(const float* __restrict__ Wh_f, const float* __restrict__ Wh_b,
                         const float* __restrict__ Wh_d,
                         float* __restrict__ whTe, float* __restrict__ whTd) {
    int idx = blockIdx.x * blockDim.x + threadIdx.x;
    if (idx >= 512 * 512) return;
    int k = idx >> 9, j = idx & 511;
#pragma unroll
    for (int g = 0; g < 3; g++) {
        whTe[(size_t)(j * 3 + g) * 512 + k] = Wh_f[k * G3 + g * 512 + j];
        whTe[(size_t)512 * 1536 + (j * 3 + g) * 512 + k] = Wh_b[k * G3 + g * 512 + j];
        whTd[(size_t)(j * 3 + g) * 512 + k] = Wh_d[k * G3 + g * 512 + j];
    }
}

// ---------------- generic fp32 GEMM ----------------
template<int GELU, int OUT16>
__global__ void gemm_k(const float* __restrict__ A, const float* __restrict__ Bm,
                       const float* __restrict__ bias, void* __restrict__ Cv,
                       int M, int N, int K) {
    __shared__ float As[16][68];
    __shared__ float Bs[16][68];
    int tid = threadIdx.x;
    int m0 = blockIdx.y * 64, n0 = blockIdx.x * 64;
    int tx = tid & 15, ty = tid >> 4;

    float acc[4][4];
#pragma unroll
    for (int i = 0; i < 4; i++)
#pragma unroll
        for (int j = 0; j < 4; j++) acc[i][j] = 0.0f;

    int lam = tid >> 2;
    int lak = (tid & 3) * 4;
    int lbk = tid >> 4;
    int lbn = (tid & 15) * 4;

    for (int k0 = 0; k0 < K; k0 += 16) {
        float4 av = (m0 + lam < M)
            ? *(const float4*)&A[(size_t)(m0 + lam) * K + k0 + lak]
            : make_float4(0.f, 0.f, 0.f, 0.f);
        float4 bv = *(const float4*)&Bm[(size_t)(k0 + lbk) * N + n0 + lbn];
        __syncthreads();
        As[lak + 0][lam] = av.x;
        As[lak + 1][lam] = av.y;
        As[lak + 2][lam] = av.z;
        As[lak + 3][lam] = av.w;
        *(float4*)&Bs[lbk][lbn] = bv;
        __syncthreads();
#pragma unroll
        for (int kk = 0; kk < 16; kk++) {
            float4 a4 = *(const float4*)&As[kk][ty * 4];
            float4 b4 = *(const float4*)&Bs[kk][tx * 4];
            float a[4] = {a4.x, a4.y, a4.z, a4.w};
            float b[4] = {b4.x, b4.y, b4.z, b4.w};
#pragma unroll
            for (int i = 0; i < 4; i++)
#pragma unroll
                for (int j = 0; j < 4; j++) acc[i][j] = fmaf(a[i], b[j], acc[i][j]);
        }
    }

#pragma unroll
    for (int i = 0; i < 4; i++) {
        int m = m0 + ty * 4 + i;
        if (m >= M) continue;
#pragma unroll
        for (int j = 0; j < 4; j++) {
            int n = n0 + tx * 4 + j;
            float v = acc[i][j] + bias[n];
            if (GELU) v = gelu_f(v);
            if (OUT16) ((__half*)Cv)[(size_t)m * N + n] = __float2half(v);
            else       ((float*)Cv)[(size_t)m * N + n] = v;
        }
    }
}

// ===== recurrence smem layout =====
#define WP2   1538
#define HP2   516
#define OFF_H   (16 * WP2)
#define OFF_P   (16 * WP2 + 16 * HP2)
#define RSMEM2  ((16 * WP2 + 16 * HP2 + 16 * 3 * 16 * 16) * 4)   // 180608 B

__device__ __forceinline__ void fill_wslab(float* ws, const float* wsrc, int tid) {
#pragma unroll
    for (int u = 0; u < 24; u++) {
        int idx4 = u * 256 + tid;
        int jl = idx4 / 384;
        int off = (idx4 - jl * 384) * 4;
        float4 v = *(const float4*)&wsrc[(size_t)jl * 1536 + off];
        float* d = &ws[jl * WP2 + off];
        *(float2*)d = make_float2(v.x, v.y);
        *(float2*)(d + 2) = make_float2(v.z, v.w);
    }
}

__device__ __forceinline__ void gru_core(const float* ws, const float* hsf,
                                         float* part, int tx, int ty) {
    unsigned long long acc[16][3];
#pragma unroll
    for (int b = 0; b < 16; b++)
#pragma unroll
        for (int g = 0; g < 3; g++) acc[b][g] = 0ull;

    const float* wr_p = ws + tx * WP2 + ty * 32;
    const float* wz_p = wr_p + 512;
    const float* wn_p = wr_p + 1024;
    const float* h_p  = hsf + ty * 32;

#pragma unroll
    for (int kk2 = 0; kk2 < 16; kk2++) {
        unsigned long long wr = *(const unsigned long long*)(wr_p + kk2 * 2);
        unsigned long long wz = *(const unsigned long long*)(wz_p + kk2 * 2);
        unsigned long long wn = *(const unsigned long long*)(wn_p + kk2 * 2);
#pragma unroll
        for (int b = 0; b < 16; b++) {
            unsigned long long h2 = *(const unsigned long long*)(h_p + b * HP2 + kk2 * 2);
            ffma2(acc[b][0], h2, wr);
            ffma2(acc[b][1], h2, wz);
            ffma2(acc[b][2], h2, wn);
        }
    }
#pragma unroll
    for (int b = 0; b < 16; b++)
#pragma unroll
        for (int g = 0; g < 3; g++)
            part[((b * 3 + g) * 16 + ty) * 16 + tx] = hsum2(acc[b][g]);
}

// ================= persistent encoder: 4 independent (dir,bg) barrier groups =================
__global__ void __launch_bounds__(256, 1)
enc_persist(const float* __restrict__ whTe,
            const float* __restrict__ bh_f, const float* __restrict__ bh_b,
            const int* __restrict__ src_lens,
            const float* __restrict__ gi_f, const float* __restrict__ gi_b,
            float* __restrict__ henc, float* __restrict__ wr_out) {
    extern __shared__ float smem[];
    float* ws   = smem;
    float* hsf  = smem + OFF_H;
    float* part = smem + OFF_P;

    int cta = blockIdx.x;
    int dir = cta & 1, bg = (cta >> 1) & 1, jt = cta >> 2;
    unsigned* bar = &g_bars[cta & 3];
    int tid = threadIdx.x;
    int tx = tid & 15, ty = tid >> 4;
    const float* bh = dir ? bh_b : bh_f;
    const float* gi = dir ? gi_b : gi_f;

    fill_wslab(ws, whTe + (size_t)dir * 512 * 1536 + (size_t)jt * 16 * 1536, tid);

    int j_g = jt * 16 + tx;
    int b_g = bg * 16 + ty;
    float br = bh[j_g], bz = bh[512 + j_g], bn = bh[1024 + j_g];
    int len = max(src_lens[b_g], 1);
    unsigned epoch = 0;
    __syncthreads();

    for (int step = 0; step < SS; step++) {
        int t = dir ? (SS - 1 - step) : step;
        int p = step & 1;
        const float* hin = henc + p * (BB * 1024);
        float* hout = henc + (p ^ 1) * (BB * 1024);

        // prefetch gi for this step (independent of recurrence -> hidden by gru_core)
        size_t row = (size_t)(b_g * SS + t);
        float gir = ldcg1(&gi[row * G3 + j_g]);
        float giz = ldcg1(&gi[row * G3 + 512 + j_g]);
        float gin = ldcg1(&gi[row * G3 + 1024 + j_g]);

#pragma unroll
        for (int u = 0; u < 8; u++) {
            int idx = u * 256 + tid;
            int bl = idx >> 7, kq = idx & 127;
            float4 h4 = ldcg4(&hin[(bg * 16 + bl) * 1024 + dir * 512 + kq * 4]);
            *(float4*)&hsf[bl * HP2 + kq * 4] = h4;
        }
        __syncthreads();

        gru_core(ws, hsf, part, tx, ty);
        __syncthreads();

        {
            float sr = 0.f, sz = 0.f, sn = 0.f;
#pragma unroll
            for (int s = 0; s < 16; s++) {
                sr += part[((ty * 3 + 0) * 16 + s) * 16 + tx];
                sz += part[((ty * 3 + 1) * 16 + s) * 16 + tx];
                sn += part[((ty * 3 + 2) * 16 + s) * 16 + tx];
            }
            float hold = hsf[ty * HP2 + j_g];
            float r = sigm(gir + sr + br);
            float z = sigm(giz + sz + bz);
            float n = tanhf(gin + r * (sn + bn));
            float hnew = (1.0f - z) * n + z * hold;
            bool valid = t < len;
            hout[b_g * 1024 + dir * 512 + j_g] = valid ? hnew : hold;
            wr_out[row * 1024 + dir * 512 + j_g] = valid ? hnew : 0.0f;
        }
        gsync(bar, epoch, 32);
    }
}

// ================= persistent decoder (t-range chunk, own barrier counter) =================
__global__ void __launch_bounds__(256, 1)
dec_persist(const float* __restrict__ whTd, const float* __restrict__ bh,
            const float* __restrict__ gi,
            const float* __restrict__ Wq, const float* __restrict__ bq,
            const float* __restrict__ Kmat, const float* __restrict__ Vmat,
            float* __restrict__ hdec, float* __restrict__ hid_all,
            float* __restrict__ hgru, int t0, int t1, int bar_idx) {
    extern __shared__ float smem[];
    float* ws   = smem;
    float* hsf  = smem + OFF_H;
    float* part = smem + OFF_P;
    __shared__ float hsh[DD];
    __shared__ float qsh[KKQ];
    __shared__ float ssh[SS];
    __shared__ float red[256];

    int cta = blockIdx.x;
    int bg = cta & 1, jt = cta >> 1;
    int tid = threadIdx.x;
    int tx = tid & 15, ty = tid >> 4;
    unsigned* bar = &g_bars[bar_idx];

    fill_wslab(ws, whTd + (size_t)jt * 16 * 1536, tid);

    int j_g = jt * 16 + tx;
    int b_g = bg * 16 + ty;
    float br = bh[j_g], bz = bh[512 + j_g], bn = bh[1024 + j_g];
    unsigned epoch = 0;
    __syncthreads();

    for (int t = t0; t < t1; t++) {
        // prefetch gi for this step
        size_t row = (size_t)(t * BB + b_g);
        float gir = ldcg1(&gi[row * G3 + j_g]);
        float giz = ldcg1(&gi[row * G3 + 512 + j_g]);
        float gin = ldcg1(&gi[row * G3 + 1024 + j_g]);

#pragma unroll
        for (int u = 0; u < 4; u++) {
            int idx = u * 256 + tid;
            int bl = idx >> 6, kq = idx & 63;
            float4 h4 = ldcg4(&hdec[(bg * 16 + bl) * 512 + kq * 8]);
            float4 h4b = ldcg4(&hdec[(bg * 16 + bl) * 512 + kq * 8 + 4]);
            *(float4*)&hsf[bl * HP2 + kq * 8] = h4;
            *(float4*)&hsf[bl * HP2 + kq * 8 + 4] = h4b;
        }
        __syncthreads();

        gru_core(ws, hsf, part, tx, ty);
        __syncthreads();

        {
            float sr = 0.f, sz = 0.f, sn = 0.f;
#pragma unroll
            for (int s = 0; s < 16; s++) {
                sr += part[((ty * 3 + 0) * 16 + s) * 16 + tx];
                sz += part[((ty * 3 + 1) * 16 + s) * 16 + tx];
                sn += part[((ty * 3 + 2) * 16 + s) * 16 + tx];
            }
            float hold = hsf[ty * HP2 + j_g];
            float r = sigm(gir + sr + br);
            float z = sigm(giz + sz + bz);
            float n = tanhf(gin + r * (sn + bn));
            hgru[b_g * 512 + j_g] = (1.0f - z) * n + z * hold;
        }
        gsync(bar, epoch, gridDim.x);

        if (cta < BB) {
            int ba = cta;
            size_t rowa = (size_t)(t * BB + ba);
            for (int i = tid; i < DD; i += 256) hsh[i] = ldcg1(&hgru[ba * 512 + i]);
            __syncthreads();
            {
                int jq = tid & 63, prt = tid >> 6;
                float acc = 0.f;
                int kb = prt * 128;
                for (int k = kb; k < kb + 128; k++) acc = fmaf(hsh[k], Wq[k * KKQ + jq], acc);
                red[tid] = acc;
            }
            __syncthreads();
            if (tid < KKQ) {
                float q = red[tid] + red[tid + 64] + red[tid + 128] + red[tid + 192] + bq[tid];
                qsh[tid] = q * 0.125f;
            }
            __syncthreads();
            if (tid < SS) {
                const float* Kp = Kmat + (size_t)(ba * SS + tid) * KKQ;
                float sc = 0.f;
                for (int k = 0; k < KKQ; k++) sc = fmaf(qsh[k], Kp[k], sc);
                ssh[tid] = sc;
            }
            __syncthreads();
            if (tid == 0) {
                float m = ssh[0];
                for (int s = 1; s < SS; s++) m = fmaxf(m, ssh[s]);
                float sum = 0.f;
                for (int s = 0; s < SS; s++) { float e = expf(ssh[s] - m); ssh[s] = e; sum += e; }
                red[0] = 1.0f / sum;
            }
            __syncthreads();
            float inv = red[0];
            __syncthreads();
            if (tid < SS) ssh[tid] *= inv;
            __syncthreads();
            for (int d0 = tid; d0 < DD; d0 += 256) {
                float a = 0.f;
                for (int s = 0; s < SS; s++)
                    a = fmaf(ssh[s], Vmat[(size_t)(ba * SS + s) * DD + d0], a);
                float hid = hsh[d0] + a;
                hdec[ba * 512 + d0] = hid;
                hid_all[rowa * 512 + d0] = hid;
            }
        }
        gsync(bar, epoch, gridDim.x);
    }
}

// transpose W2 [K=512, N=32000] fp32 -> W2h [N, K] fp16
__global__ void transpose_w2(const float* __restrict__ W2, __half* __restrict__ W2h) {
    __shared__ float ts[32][33];
    int n0 = blockIdx.x * 32;
    int k0 = blockIdx.y * 32;
    int tx = threadIdx.x, ty = threadIdx.y;
#pragma unroll
    for (int j = 0; j < 4; j++)
        ts[ty + j * 8][tx] = W2[(size_t)(k0 + ty + j * 8) * VOC + n0 + tx];
    __syncthreads();
#pragma unroll
    for (int j = 0; j < 4; j++) {
        int n = n0 + ty + j * 8;
        int k = k0 + tx;
        W2h[(size_t)n * DD + k] = __float2half(ts[tx][ty + j * 8]);
    }
}

// ================= HMMA fp16 head GEMM (m-tile offset) =================
#define HPITCH 72

__device__ __forceinline__ uint32_t smem_u32(const void* p) {
    uint32_t a;
    asm("{ .reg .u64 t; cvta.to.shared.u64 t, %1; cvt.u32.u64 %0, t; }" : "=r"(a) : "l"(p));
    return a;
}
__device__ __forceinline__ void ldmatrix_x4(uint32_t* r, uint32_t addr) {
    asm volatile("ldmatrix.sync.aligned.m8n8.x4.shared.b16 {%0,%1,%2,%3}, [%4];"
                 : "=r"(r[0]), "=r"(r[1]), "=r"(r[2]), "=r"(r[3]) : "r"(addr));
}
__device__ __forceinline__ void ldmatrix_x2(uint32_t* r, uint32_t addr) {
    asm volatile("ldmatrix.sync.aligned.m8n8.x2.shared.b16 {%0,%1}, [%2];"
                 : "=r"(r[0]), "=r"(r[1]) : "r"(addr));
}
__device__ __forceinline__ void mma16816(float* c, const uint32_t* a, const uint32_t* b) {
    asm volatile(
        "mma.sync.aligned.m16n8k16.row.col.f32.f16.f16.f32 "
        "{%0,%1,%2,%3}, {%4,%5,%6,%7}, {%8,%9}, {%0,%1,%2,%3};"
        : "+f"(c[0]), "+f"(c[1]), "+f"(c[2]), "+f"(c[3])
        : "r"(a[0]), "r"(a[1]), "r"(a[2]), "r"(a[3]), "r"(b[0]), "r"(b[1]));
}

__global__ void __launch_bounds__(256, 2)
head_mma(const __half* __restrict__ Xh, const __half* __restrict__ W2h,
         const float* __restrict__ b2, float* __restrict__ out, int moff) {
    __shared__ __half As[128 * HPITCH];
    __shared__ __half Bs[128 * HPITCH];

    int tid = threadIdx.x;
    int wid = tid >> 5, lane = tid & 31;
    int m0 = (blockIdx.x + moff) * 128;
    int n0 = blockIdx.y * 128;
    int wm = (wid >> 2) * 64;
    int wn = (wid & 3) * 32;

    float c[4][4][4];
#pragma unroll
    for (int mi = 0; mi < 4; mi++)
#pragma unroll
        for (int ni = 0; ni < 4; ni++)
#pragma unroll
            for (int q = 0; q < 4; q++) c[mi][ni][q] = 0.0f;

    uint32_t as_base = smem_u32(As);
    uint32_t bs_base = smem_u32(Bs);

    for (int kc = 0; kc < 8; kc++) {
        int k0 = kc * 64;
        __syncthreads();
#pragma unroll
        for (int it = 0; it < 4; it++) {
            int idx = it * 256 + tid;
            int row = idx >> 3;
            int col = (idx & 7) * 8;
            uint4 va = (m0 + row < MROWS)
                ? *(const uint4*)(Xh + (size_t)(m0 + row) * DD + k0 + col)
                : make_uint4(0, 0, 0, 0);
            *(uint4*)(As + row * HPITCH + col) = va;
            uint4 vb = *(const uint4*)(W2h + (size_t)(n0 + row) * DD + k0 + col);
            *(uint4*)(Bs + row * HPITCH + col) = vb;
        }
        __syncthreads();

#pragma unroll
        for (int k16 = 0; k16 < 4; k16++) {
            uint32_t afrag[4][4], bfrag[4][2];
#pragma unroll
            for (int mi = 0; mi < 4; mi++) {
                int r = wm + mi * 16 + (lane & 15);
                int cl = k16 * 16 + ((lane >> 4) * 8);
                ldmatrix_x4(afrag[mi], as_base + (uint32_t)(r * HPITCH + cl) * 2);
            }
#pragma unroll
            for (int ni = 0; ni < 4; ni++) {
                int r = wn + ni * 8 + (lane & 7);
                int cl = k16 * 16 + (((lane >> 3) & 1) * 8);
                ldmatrix_x2(bfrag[ni], bs_base + (uint32_t)(r * HPITCH + cl) * 2);
            }
#pragma unroll
            for (int mi = 0; mi < 4; mi++)
#pragma unroll
                for (int ni = 0; ni < 4; ni++)
                    mma16816(c[mi][ni], afrag[mi], bfrag[ni]);
        }
    }

    int rbase = lane >> 2;
    int cbase = (lane & 3) * 2;
#pragma unroll
    for (int mi = 0; mi < 4; mi++) {
#pragma unroll
        for (int half2i = 0; half2i < 2; half2i++) {
            int m = m0 + wm + mi * 16 + rbase + half2i * 8;
            if (m >= MROWS) continue;
            int b = m & 31, t = m >> 5;
            float* orow = out + (size_t)(b * TT + t + 1) * VOC;
#pragma unroll
            for (int ni = 0; ni < 4; ni++) {
                int n = n0 + wn + ni * 8 + cbase;
                float2 v;
                v.x = c[mi][ni][half2i * 2 + 0] + b2[n];
                v.y = c[mi][ni][half2i * 2 + 1] + b2[n + 1];
                *(float2*)(orow + n) = v;
            }
        }
    }
}

// ================================ host ================================
extern "C" void kernel_launch(void* const* d_in, const int* in_sizes, int n_in,
                              void* d_out, int out_size) {
    const int*   src       = (const int*)  d_in[0];
    const int*   trg       = (const int*)  d_in[1];
    const int*   src_lens  = (const int*)  d_in[2];
    const float* enc_embed = (const float*)d_in[3];
    const float* Wi_f      = (const float*)d_in[4];
    const float* Wh_f      = (const float*)d_in[5];
    const float* bi_f      = (const float*)d_in[6];
    const float* bh_f      = (const float*)d_in[7];
    const float* Wi_b      = (const float*)d_in[8];
    const float* Wh_b      = (const float*)d_in[9];
    const float* bi_b      = (const float*)d_in[10];
    const float* bh_b      = (const float*)d_in[11];
    const float* W_e2d     = (const float*)d_in[12];
    const float* b_e2d     = (const float*)d_in[13];
    const float* dec_embed = (const float*)d_in[14];
    const float* Wi_d      = (const float*)d_in[15];
    const float* Wh_d      = (const float*)d_in[16];
    const float* bi_d      = (const float*)d_in[17];
    const float* bh_d      = (const float*)d_in[18];
    const float* Wq        = (const float*)d_in[19];
    const float* bq        = (const float*)d_in[20];
    const float* Wk        = (const float*)d_in[21];
    const float* bk        = (const float*)d_in[22];
    const float* Wv        = (const float*)d_in[23];
    const float* bv        = (const float*)d_in[24];
    const float* W1        = (const float*)d_in[25];
    const float* b1        = (const float*)d_in[26];
    const float* W2        = (const float*)d_in[27];
    const float* b2        = (const float*)d_in[28];
    float* out = (float*)d_out;

    float* scr = nullptr;
    cudaGetSymbolAddress((void**)&scr, g_scr);
    __half* xh = nullptr;
    cudaGetSymbolAddress((void**)&xh, g_xh);
    __half* w2h = nullptr;
    cudaGetSymbolAddress((void**)&w2h, g_w2h);

    float* p_emb  = scr;
    float* p_gif  = p_emb  + NF_EMB;
    float* p_gib  = p_gif  + NF_GI;
    float* p_wr   = p_gib  + NF_GI;
    float* p_henc = p_wr   + NF_WR;
    float* p_K    = p_henc + NF_HENC;
    float* p_V    = p_K    + NF_K;
    float* p_demb = p_V    + NF_V;
    float* p_gid  = p_demb + NF_DEMB;
    float* p_hdec = p_gid  + NF_GID;
    float* p_hid  = p_hdec + NF_HDEC;
    float* p_whTe = p_hid  + NF_HID;
    float* p_whTd = p_whTe + NF_WHTE;
    float* p_hgru = p_whTd + NF_WHTD;

    static cudaStream_t s2;
    static cudaEvent_t evFork, evPack, evGid, evD[3], evJoin;
    static int once = 0;
    if (!once) {
        cudaFuncSetAttribute(enc_persist, cudaFuncAttributeMaxDynamicSharedMemorySize, RSMEM2);
        cudaFuncSetAttribute(dec_persist, cudaFuncAttributeMaxDynamicSharedMemorySize, RSMEM2);
        cudaStreamCreateWithFlags(&s2, cudaStreamNonBlocking);
        cudaEventCreateWithFlags(&evFork, cudaEventDisableTiming);
        cudaEventCreateWithFlags(&evPack, cudaEventDisableTiming);
        cudaEventCreateWithFlags(&evGid,  cudaEventDisableTiming);
        for (int i = 0; i < 3; i++) cudaEventCreateWithFlags(&evD[i], cudaEventDisableTiming);
        cudaEventCreateWithFlags(&evJoin, cudaEventDisableTiming);
        once = 1;
    }

    // 0) init on main stream, then fork s2
    init_zero<<<(BB * VOC + 255) / 256, 256>>>(out, p_henc);
    cudaEventRecord(evFork, 0);
    cudaStreamWaitEvent(s2, evFork, 0);

    // ---- s2 branch: weight prep + decoder input projections ----
    transpose_w2<<<dim3(VOC / 32, DD / 32), dim3(32, 8), 0, s2>>>(W2, w2h);
    pack_whT<<<(512 * 512 + 255) / 256, 256, 0, s2>>>(Wh_f, Wh_b, Wh_d, p_whTe, p_whTd);
    cudaEventRecord(evPack, s2);
    gather_trg<<<(BB * (TT - 1) * (EE / 4) + 255) / 256, 256, 0, s2>>>(trg, dec_embed, p_demb);
    gemm_k<0,0><<<dim3(G3 / 64, (BB * (TT - 1) + 63) / 64), 256, 0, s2>>>(
        p_demb, Wi_d, bi_d, p_gid, BB * (TT - 1), G3, EE);
    cudaEventRecord(evGid, s2);

    // ---- main stream: encoder path ----
    gather_src<<<(BB * SS * (EE / 4) + 255) / 256, 256>>>(src, enc_embed, p_emb);
    gemm_k<0,0><<<dim3(G3 / 64, (BB * SS) / 64), 256>>>(p_emb, Wi_f, bi_f, p_gif, BB * SS, G3, EE);
    gemm_k<0,0><<<dim3(G3 / 64, (BB * SS) / 64), 256>>>(p_emb, Wi_b, bi_b, p_gib, BB * SS, G3, EE);
    cudaStreamWaitEvent(0, evPack, 0);
    enc_persist<<<128, 256, RSMEM2>>>(p_whTe, bh_f, bh_b, src_lens, p_gif, p_gib, p_henc, p_wr);
    float* p_sent = p_henc;

    gemm_k<0,0><<<dim3(KKQ / 64, (BB * SS) / 64), 256>>>(p_wr, Wk, bk, p_K, BB * SS, KKQ, 2 * HH);
    gemm_k<0,0><<<dim3(DD / 64, (BB * SS) / 64), 256>>>(p_wr, Wv, bv, p_V, BB * SS, DD, 2 * HH);
    gemm_k<1,0><<<dim3(DD / 64, 1), 256>>>(p_sent, W_e2d, b_e2d, p_hdec, BB, DD, 2 * HH);

    cudaStreamWaitEvent(0, evGid, 0);

    // ---- 4-way decoder/head pipeline, tail-light: chunks 20/20/20/3 steps ----
    // chunk c covers t in [t0, t1) => hid rows [t0*32, t1*32) => head m-tiles [t0/4, t1/4)
    const int tsplit[5] = {0, 20, 40, 60, TT - 1};
    for (int c = 0; c < 4; c++) {
        int t0 = tsplit[c], t1 = tsplit[c + 1];
        dec_persist<<<64, 256, RSMEM2>>>(p_whTd, bh_d, p_gid, Wq, bq, p_K, p_V,
                                         p_hdec, p_hid, p_hgru, t0, t1, 4 + c);
        int m0 = t0 * BB;
        int mrows = (t1 - t0) * BB;                 // 640,640,640,96
        int tile0 = m0 / 128;                       // 0,5,10,15
        int ntiles = (c == 3) ? (16 - tile0) : (mrows / 128);   // 5,5,5,1
        if (c < 3) {
            cudaEventRecord(evD[c], 0);
            cudaStreamWaitEvent(s2, evD[c], 0);
            gemm_k<1,1><<<dim3(DD / 64, mrows / 64), 256, 0, s2>>>(
                p_hid + (size_t)m0 * DD, W1, b1, xh + (size_t)m0 * DD, mrows, DD, DD);
            head_mma<<<dim3(ntiles, VOC / 128), 256, 0, s2>>>(xh, w2h, b2, out, tile0);
            if (c == 2) cudaEventRecord(evJoin, s2);
        } else {
            gemm_k<1,1><<<dim3(DD / 64, (mrows + 63) / 64), 256>>>(
                p_hid + (size_t)m0 * DD, W1, b1, xh + (size_t)m0 * DD, mrows, DD, DD);
            head_mma<<<dim3(ntiles, VOC / 128), 256>>>(xh, w2h, b2, out, tile0);
        }
    }

    // join s2
    cudaStreamWaitEvent(0, evJoin, 0);
}

// round 13
// speedup vs baseline: 1.0027x; 1.0027x over previous
#include <cuda_runtime.h>
#include <cuda_fp16.h>
#include <cstdint>
#include <math.h>

#define BB   32
#define SS   64
#define TT   64
#define EE   256
#define HH   512
#define DD   512
#define KKQ  64
#define VOC  32000
#define G3   1536
#define MROWS (BB*(TT-1))   // 2016

#define NF_EMB   (BB*SS*EE)
#define NF_GI    (BB*SS*G3)
#define NF_WR    (BB*SS*2*HH)
#define NF_HENC  (2*BB*2*HH)
#define NF_K     (BB*SS*KKQ)
#define NF_V     (BB*SS*DD)
#define NF_DEMB  (BB*(TT-1)*EE)
#define NF_GID   (BB*(TT-1)*G3)
#define NF_HDEC  (BB*DD)
#define NF_HID   (BB*(TT-1)*DD)
#define NF_WHTE  (2*512*1536)
#define NF_WHTD  (512*1536)
#define NF_HGRU  (BB*DD)

#define NF_TOTAL (NF_EMB + 2*NF_GI + NF_WR + NF_HENC + NF_K + NF_V + NF_DEMB + NF_GID + \
                  NF_HDEC + NF_HID + NF_WHTE + NF_WHTD + NF_HGRU)

__device__ float g_scr[NF_TOTAL];
__device__ __half g_xh[MROWS * DD];
__device__ __half g_w2h[VOC * DD];
__device__ unsigned g_bars[8];   // 0..3 enc (dir,bg) groups; 4..7 dec chunks

__device__ __forceinline__ float sigm(float x) { return 1.0f / (1.0f + expf(-x)); }
__device__ __forceinline__ float gelu_f(float x) { return 0.5f * x * (1.0f + erff(x * 0.7071067811865475f)); }

__device__ __forceinline__ float ldcg1(const float* p) {
    float v; asm volatile("ld.global.cg.f32 %0, [%1];" : "=f"(v) : "l"(p)); return v;
}
__device__ __forceinline__ float4 ldcg4(const float* p) {
    float4 v;
    asm volatile("ld.global.cg.v4.f32 {%0,%1,%2,%3}, [%4];"
                 : "=f"(v.x), "=f"(v.y), "=f"(v.z), "=f"(v.w) : "l"(p));
    return v;
}

__device__ __forceinline__ void ffma2(unsigned long long& d,
                                      unsigned long long a, unsigned long long b) {
    asm("fma.rn.f32x2 %0, %1, %2, %0;" : "+l"(d) : "l"(a), "l"(b));
}
__device__ __forceinline__ float hsum2(unsigned long long v) {
    float lo = __uint_as_float((unsigned)(v & 0xffffffffull));
    float hi = __uint_as_float((unsigned)(v >> 32));
    return lo + hi;
}

__device__ __forceinline__ void gsync(unsigned* bar, unsigned& epoch, unsigned nb) {
    __syncthreads();
    if (threadIdx.x == 0) {
        epoch += nb;
        __threadfence();
        atomicAdd(bar, 1u);
        while (*(volatile unsigned*)bar < epoch) __nanosleep(32);
        __threadfence();
    }
    __syncthreads();
}

// ---------------- init ----------------
__global__ void init_zero(float* __restrict__ out, float* __restrict__ henc) {
    int i = blockIdx.x * blockDim.x + threadIdx.x;
    if (i < 8) g_bars[i] = 0;
    if (i < BB * VOC) {
        int b = i / VOC;
        out[(size_t)b * TT * VOC + (i % VOC)] = 0.0f;
    }
    if (i < NF_HENC) henc[i] = 0.0f;
}

// ---------------- embedding gathers ----------------
__global__ void gather_src(const int* __restrict__ src, const float* __restrict__ tab,
                           float* __restrict__ emb) {
    int i = blockIdx.x * blockDim.x + threadIdx.x;
    if (i >= BB * SS * (EE / 4)) return;
    int row = i / (EE / 4);
    int c   = i % (EE / 4);
    ((float4*)emb)[row * (EE / 4) + c] =
        ((const float4*)tab)[(size_t)src[row] * (EE / 4) + c];
}

__global__ void gather_trg(const int* __restrict__ trg, const float* __restrict__ tab,
                           float* __restrict__ demb) {
    int i = blockIdx.x * blockDim.x + threadIdx.x;
    if (i >= BB * (TT - 1) * (EE / 4)) return;
    int m = i / (EE / 4);
    int c = i % (EE / 4);
    int t = m / BB, b = m % BB;
    int tok = trg[b * TT + t];
    ((float4*)demb)[m * (EE / 4) + c] =
        ((const float4*)tab)[(size_t)tok * (EE / 4) + c];
}

// ---------------- transpose-pack recurrent weights: [dir][j][gate][k] ----------------
__global__ void pack_whT(const float* __restrict__ Wh_f, const float* __restrict__ Wh_b,
                         const float* __restrict__ Wh_d,
                         float* __restrict__ whTe, float* __restrict__ whTd) {
    int idx = blockIdx.x * blockDim.x + threadIdx.x;
    if (idx >= 512 * 512) return;
    int k = idx >> 9, j = idx & 511;
#pragma unroll
    for (int g = 0; g < 3; g++) {
        whTe[(size_t)(j * 3 + g) * 512 + k] = Wh_f[k * G3 + g * 512 + j];
        whTe[(size_t)512 * 1536 + (j * 3 + g) * 512 + k] = Wh_b[k * G3 + g * 512 + j];
        whTd[(size_t)(j * 3 + g) * 512 + k] = Wh_d[k * G3 + g * 512 + j];
    }
}

// ---------------- generic fp32 GEMM ----------------
template<int GELU, int OUT16>
__global__ void gemm_k(const float* __restrict__ A, const float* __restrict__ Bm,
                       const float* __restrict__ bias, void* __restrict__ Cv,
                       int M, int N, int K) {
    __shared__ float As[16][68];
    __shared__ float Bs[16][68];
    int tid = threadIdx.x;
    int m0 = blockIdx.y * 64, n0 = blockIdx.x * 64;
    int tx = tid & 15, ty = tid >> 4;

    float acc[4][4];
#pragma unroll
    for (int i = 0; i < 4; i++)
#pragma unroll
        for (int j = 0; j < 4; j++) acc[i][j] = 0.0f;

    int lam = tid >> 2;
    int lak = (tid & 3) * 4;
    int lbk = tid >> 4;
    int lbn = (tid & 15) * 4;

    for (int k0 = 0; k0 < K; k0 += 16) {
        float4 av = (m0 + lam < M)
            ? *(const float4*)&A[(size_t)(m0 + lam) * K + k0 + lak]
            : make_float4(0.f, 0.f, 0.f, 0.f);
        float4 bv = *(const float4*)&Bm[(size_t)(k0 + lbk) * N + n0 + lbn];
        __syncthreads();
        As[lak + 0][lam] = av.x;
        As[lak + 1][lam] = av.y;
        As[lak + 2][lam] = av.z;
        As[lak + 3][lam] = av.w;
        *(float4*)&Bs[lbk][lbn] = bv;
        __syncthreads();
#pragma unroll
        for (int kk = 0; kk < 16; kk++) {
            float4 a4 = *(const float4*)&As[kk][ty * 4];
            float4 b4 = *(const float4*)&Bs[kk][tx * 4];
            float a[4] = {a4.x, a4.y, a4.z, a4.w};
            float b[4] = {b4.x, b4.y, b4.z, b4.w};
#pragma unroll
            for (int i = 0; i < 4; i++)
#pragma unroll
                for (int j = 0; j < 4; j++) acc[i][j] = fmaf(a[i], b[j], acc[i][j]);
        }
    }

#pragma unroll
    for (int i = 0; i < 4; i++) {
        int m = m0 + ty * 4 + i;
        if (m >= M) continue;
#pragma unroll
        for (int j = 0; j < 4; j++) {
            int n = n0 + tx * 4 + j;
            float v = acc[i][j] + bias[n];
            if (GELU) v = gelu_f(v);
            if (OUT16) ((__half*)Cv)[(size_t)m * N + n] = __float2half(v);
            else       ((float*)Cv)[(size_t)m * N + n] = v;
        }
    }
}

// ===== recurrence smem layout =====
#define WP2   1538
#define HP2   516
#define OFF_H   (16 * WP2)
#define OFF_P   (16 * WP2 + 16 * HP2)
#define RSMEM2  ((16 * WP2 + 16 * HP2 + 16 * 3 * 16 * 16) * 4)   // 180608 B

__device__ __forceinline__ void fill_wslab(float* ws, const float* wsrc, int tid) {
#pragma unroll
    for (int u = 0; u < 24; u++) {
        int idx4 = u * 256 + tid;
        int jl = idx4 / 384;
        int off = (idx4 - jl * 384) * 4;
        float4 v = *(const float4*)&wsrc[(size_t)jl * 1536 + off];
        float* d = &ws[jl * WP2 + off];
        *(float2*)d = make_float2(v.x, v.y);
        *(float2*)(d + 2) = make_float2(v.z, v.w);
    }
}

__device__ __forceinline__ void gru_core(const float* ws, const float* hsf,
                                         float* part, int tx, int ty) {
    unsigned long long acc[16][3];
#pragma unroll
    for (int b = 0; b < 16; b++)
#pragma unroll
        for (int g = 0; g < 3; g++) acc[b][g] = 0ull;

    const float* wr_p = ws + tx * WP2 + ty * 32;
    const float* wz_p = wr_p + 512;
    const float* wn_p = wr_p + 1024;
    const float* h_p  = hsf + ty * 32;

#pragma unroll
    for (int kk2 = 0; kk2 < 16; kk2++) {
        unsigned long long wr = *(const unsigned long long*)(wr_p + kk2 * 2);
        unsigned long long wz = *(const unsigned long long*)(wz_p + kk2 * 2);
        unsigned long long wn = *(const unsigned long long*)(wn_p + kk2 * 2);
#pragma unroll
        for (int b = 0; b < 16; b++) {
            unsigned long long h2 = *(const unsigned long long*)(h_p + b * HP2 + kk2 * 2);
            ffma2(acc[b][0], h2, wr);
            ffma2(acc[b][1], h2, wz);
            ffma2(acc[b][2], h2, wn);
        }
    }
#pragma unroll
    for (int b = 0; b < 16; b++)
#pragma unroll
        for (int g = 0; g < 3; g++)
            part[((b * 3 + g) * 16 + ty) * 16 + tx] = hsum2(acc[b][g]);
}

// ================= persistent encoder: 4 independent (dir,bg) barrier groups =================
__global__ void __launch_bounds__(256, 1)
enc_persist(const float* __restrict__ whTe,
            const float* __restrict__ bh_f, const float* __restrict__ bh_b,
            const int* __restrict__ src_lens,
            const float* __restrict__ gi_f, const float* __restrict__ gi_b,
            float* __restrict__ henc, float* __restrict__ wr_out) {
    extern __shared__ float smem[];
    float* ws   = smem;
    float* hsf  = smem + OFF_H;
    float* part = smem + OFF_P;

    int cta = blockIdx.x;
    int dir = cta & 1, bg = (cta >> 1) & 1, jt = cta >> 2;
    unsigned* bar = &g_bars[cta & 3];
    int tid = threadIdx.x;
    int tx = tid & 15, ty = tid >> 4;
    const float* bh = dir ? bh_b : bh_f;
    const float* gi = dir ? gi_b : gi_f;

    fill_wslab(ws, whTe + (size_t)dir * 512 * 1536 + (size_t)jt * 16 * 1536, tid);

    int j_g = jt * 16 + tx;
    int b_g = bg * 16 + ty;
    float br = bh[j_g], bz = bh[512 + j_g], bn = bh[1024 + j_g];
    int len = max(src_lens[b_g], 1);
    unsigned epoch = 0;
    __syncthreads();

    for (int step = 0; step < SS; step++) {
        int t = dir ? (SS - 1 - step) : step;
        int p = step & 1;
        const float* hin = henc + p * (BB * 1024);
        float* hout = henc + (p ^ 1) * (BB * 1024);

        // prefetch gi for this step (independent of the recurrence)
        size_t row = (size_t)(b_g * SS + t);
        float gir = ldcg1(&gi[row * G3 + j_g]);
        float giz = ldcg1(&gi[row * G3 + 512 + j_g]);
        float gin = ldcg1(&gi[row * G3 + 1024 + j_g]);

#pragma unroll
        for (int u = 0; u < 8; u++) {
            int idx = u * 256 + tid;
            int bl = idx >> 7, kq = idx & 127;
            float4 h4 = ldcg4(&hin[(bg * 16 + bl) * 1024 + dir * 512 + kq * 4]);
            *(float4*)&hsf[bl * HP2 + kq * 4] = h4;
        }
        __syncthreads();

        gru_core(ws, hsf, part, tx, ty);
        __syncthreads();

        {
            float sr = 0.f, sz = 0.f, sn = 0.f;
#pragma unroll
            for (int s = 0; s < 16; s++) {
                sr += part[((ty * 3 + 0) * 16 + s) * 16 + tx];
                sz += part[((ty * 3 + 1) * 16 + s) * 16 + tx];
                sn += part[((ty * 3 + 2) * 16 + s) * 16 + tx];
            }
            float hold = hsf[ty * HP2 + j_g];
            float r = sigm(gir + sr + br);
            float z = sigm(giz + sz + bz);
            float n = tanhf(gin + r * (sn + bn));
            float hnew = (1.0f - z) * n + z * hold;
            bool valid = t < len;
            hout[b_g * 1024 + dir * 512 + j_g] = valid ? hnew : hold;
            wr_out[row * 1024 + dir * 512 + j_g] = valid ? hnew : 0.0f;
        }
        gsync(bar, epoch, 32);
    }
}

// ================= persistent decoder (t-range chunk, own barrier counter) =================
__global__ void __launch_bounds__(256, 1)
dec_persist(const float* __restrict__ whTd, const float* __restrict__ bh,
            const float* __restrict__ gi,
            const float* __restrict__ Wq, const float* __restrict__ bq,
            const float* __restrict__ Kmat, const float* __restrict__ Vmat,
            float* __restrict__ hdec, float* __restrict__ hid_all,
            float* __restrict__ hgru, int t0, int t1, int bar_idx) {
    extern __shared__ float smem[];
    float* ws   = smem;
    float* hsf  = smem + OFF_H;
    float* part = smem + OFF_P;
    __shared__ float hsh[DD];
    __shared__ float qsh[KKQ];
    __shared__ float ssh[SS];
    __shared__ float red[256];

    int cta = blockIdx.x;
    int bg = cta & 1, jt = cta >> 1;
    int tid = threadIdx.x;
    int tx = tid & 15, ty = tid >> 4;
    unsigned* bar = &g_bars[bar_idx];

    fill_wslab(ws, whTd + (size_t)jt * 16 * 1536, tid);

    int j_g = jt * 16 + tx;
    int b_g = bg * 16 + ty;
    float br = bh[j_g], bz = bh[512 + j_g], bn = bh[1024 + j_g];
    unsigned epoch = 0;
    __syncthreads();

    for (int t = t0; t < t1; t++) {
        // prefetch gi for this step
        size_t row = (size_t)(t * BB + b_g);
        float gir = ldcg1(&gi[row * G3 + j_g]);
        float giz = ldcg1(&gi[row * G3 + 512 + j_g]);
        float gin = ldcg1(&gi[row * G3 + 1024 + j_g]);

#pragma unroll
        for (int u = 0; u < 4; u++) {
            int idx = u * 256 + tid;
            int bl = idx >> 6, kq = idx & 63;
            float4 h4 = ldcg4(&hdec[(bg * 16 + bl) * 512 + kq * 8]);
            float4 h4b = ldcg4(&hdec[(bg * 16 + bl) * 512 + kq * 8 + 4]);
            *(float4*)&hsf[bl * HP2 + kq * 8] = h4;
            *(float4*)&hsf[bl * HP2 + kq * 8 + 4] = h4b;
        }
        __syncthreads();

        gru_core(ws, hsf, part, tx, ty);
        __syncthreads();

        {
            float sr = 0.f, sz = 0.f, sn = 0.f;
#pragma unroll
            for (int s = 0; s < 16; s++) {
                sr += part[((ty * 3 + 0) * 16 + s) * 16 + tx];
                sz += part[((ty * 3 + 1) * 16 + s) * 16 + tx];
                sn += part[((ty * 3 + 2) * 16 + s) * 16 + tx];
            }
            float hold = hsf[ty * HP2 + j_g];
            float r = sigm(gir + sr + br);
            float z = sigm(giz + sz + bz);
            float n = tanhf(gin + r * (sn + bn));
            hgru[b_g * 512 + j_g] = (1.0f - z) * n + z * hold;
        }
        gsync(bar, epoch, gridDim.x);

        if (cta < BB) {
            int ba = cta;
            size_t rowa = (size_t)(t * BB + ba);
            for (int i = tid; i < DD; i += 256) hsh[i] = ldcg1(&hgru[ba * 512 + i]);
            __syncthreads();
            {
                int jq = tid & 63, prt = tid >> 6;
                float acc = 0.f;
                int kb = prt * 128;
                for (int k = kb; k < kb + 128; k++) acc = fmaf(hsh[k], Wq[k * KKQ + jq], acc);
                red[tid] = acc;
            }
            __syncthreads();
            if (tid < KKQ) {
                float q = red[tid] + red[tid + 64] + red[tid + 128] + red[tid + 192] + bq[tid];
                qsh[tid] = q * 0.125f;
            }
            __syncthreads();
            if (tid < SS) {
                const float* Kp = Kmat + (size_t)(ba * SS + tid) * KKQ;
                float sc = 0.f;
                for (int k = 0; k < KKQ; k++) sc = fmaf(qsh[k], Kp[k], sc);
                ssh[tid] = sc;
            }
            __syncthreads();
            if (tid == 0) {
                float m = ssh[0];
                for (int s = 1; s < SS; s++) m = fmaxf(m, ssh[s]);
                float sum = 0.f;
                for (int s = 0; s < SS; s++) { float e = expf(ssh[s] - m); ssh[s] = e; sum += e; }
                red[0] = 1.0f / sum;
            }
            __syncthreads();
            float inv = red[0];
            __syncthreads();
            if (tid < SS) ssh[tid] *= inv;
            __syncthreads();
            for (int d0 = tid; d0 < DD; d0 += 256) {
                float a = 0.f;
                for (int s = 0; s < SS; s++)
                    a = fmaf(ssh[s], Vmat[(size_t)(ba * SS + s) * DD + d0], a);
                float hid = hsh[d0] + a;
                hdec[ba * 512 + d0] = hid;
                hid_all[rowa * 512 + d0] = hid;
            }
        }
        gsync(bar, epoch, gridDim.x);
    }
}

// transpose W2 [K=512, N=32000] fp32 -> W2h [N, K] fp16
__global__ void transpose_w2(const float* __restrict__ W2, __half* __restrict__ W2h) {
    __shared__ float ts[32][33];
    int n0 = blockIdx.x * 32;
    int k0 = blockIdx.y * 32;
    int tx = threadIdx.x, ty = threadIdx.y;
#pragma unroll
    for (int j = 0; j < 4; j++)
        ts[ty + j * 8][tx] = W2[(size_t)(k0 + ty + j * 8) * VOC + n0 + tx];
    __syncthreads();
#pragma unroll
    for (int j = 0; j < 4; j++) {
        int n = n0 + ty + j * 8;
        int k = k0 + tx;
        W2h[(size_t)n * DD + k] = __float2half(ts[tx][ty + j * 8]);
    }
}

// ================= HMMA fp16 head GEMM (m-tile offset) =================
#define HPITCH 72

__device__ __forceinline__ uint32_t smem_u32(const void* p) {
    uint32_t a;
    asm("{ .reg .u64 t; cvta.to.shared.u64 t, %1; cvt.u32.u64 %0, t; }" : "=r"(a) : "l"(p));
    return a;
}
__device__ __forceinline__ void ldmatrix_x4(uint32_t* r, uint32_t addr) {
    asm volatile("ldmatrix.sync.aligned.m8n8.x4.shared.b16 {%0,%1,%2,%3}, [%4];"
                 : "=r"(r[0]), "=r"(r[1]), "=r"(r[2]), "=r"(r[3]) : "r"(addr));
}
__device__ __forceinline__ void ldmatrix_x2(uint32_t* r, uint32_t addr) {
    asm volatile("ldmatrix.sync.aligned.m8n8.x2.shared.b16 {%0,%1}, [%2];"
                 : "=r"(r[0]), "=r"(r[1]) : "r"(addr));
}
__device__ __forceinline__ void mma16816(float* c, const uint32_t* a, const uint32_t* b) {
    asm volatile(
        "mma.sync.aligned.m16n8k16.row.col.f32.f16.f16.f32 "
        "{%0,%1,%2,%3}, {%4,%5,%6,%7}, {%8,%9}, {%0,%1,%2,%3};"
        : "+f"(c[0]), "+f"(c[1]), "+f"(c[2]), "+f"(c[3])
        : "r"(a[0]), "r"(a[1]), "r"(a[2]), "r"(a[3]), "r"(b[0]), "r"(b[1]));
}

__global__ void __launch_bounds__(256, 2)
head_mma(const __half* __restrict__ Xh, const __half* __restrict__ W2h,
         const float* __restrict__ b2, float* __restrict__ out, int moff) {
    __shared__ __half As[128 * HPITCH];
    __shared__ __half Bs[128 * HPITCH];

    int tid = threadIdx.x;
    int wid = tid >> 5, lane = tid & 31;
    int m0 = (blockIdx.x + moff) * 128;
    int n0 = blockIdx.y * 128;
    int wm = (wid >> 2) * 64;
    int wn = (wid & 3) * 32;

    float c[4][4][4];
#pragma unroll
    for (int mi = 0; mi < 4; mi++)
#pragma unroll
        for (int ni = 0; ni < 4; ni++)
#pragma unroll
            for (int q = 0; q < 4; q++) c[mi][ni][q] = 0.0f;

    uint32_t as_base = smem_u32(As);
    uint32_t bs_base = smem_u32(Bs);

    for (int kc = 0; kc < 8; kc++) {
        int k0 = kc * 64;
        __syncthreads();
#pragma unroll
        for (int it = 0; it < 4; it++) {
            int idx = it * 256 + tid;
            int row = idx >> 3;
            int col = (idx & 7) * 8;
            uint4 va = (m0 + row < MROWS)
                ? *(const uint4*)(Xh + (size_t)(m0 + row) * DD + k0 + col)
                : make_uint4(0, 0, 0, 0);
            *(uint4*)(As + row * HPITCH + col) = va;
            uint4 vb = *(const uint4*)(W2h + (size_t)(n0 + row) * DD + k0 + col);
            *(uint4*)(Bs + row * HPITCH + col) = vb;
        }
        __syncthreads();

#pragma unroll
        for (int k16 = 0; k16 < 4; k16++) {
            uint32_t afrag[4][4], bfrag[4][2];
#pragma unroll
            for (int mi = 0; mi < 4; mi++) {
                int r = wm + mi * 16 + (lane & 15);
                int cl = k16 * 16 + ((lane >> 4) * 8);
                ldmatrix_x4(afrag[mi], as_base + (uint32_t)(r * HPITCH + cl) * 2);
            }
#pragma unroll
            for (int ni = 0; ni < 4; ni++) {
                int r = wn + ni * 8 + (lane & 7);
                int cl = k16 * 16 + (((lane >> 3) & 1) * 8);
                ldmatrix_x2(bfrag[ni], bs_base + (uint32_t)(r * HPITCH + cl) * 2);
            }
#pragma unroll
            for (int mi = 0; mi < 4; mi++)
#pragma unroll
                for (int ni = 0; ni < 4; ni++)
                    mma16816(c[mi][ni], afrag[mi], bfrag[ni]);
        }
    }

    int rbase = lane >> 2;
    int cbase = (lane & 3) * 2;
#pragma unroll
    for (int mi = 0; mi < 4; mi++) {
#pragma unroll
        for (int half2i = 0; half2i < 2; half2i++) {
            int m = m0 + wm + mi * 16 + rbase + half2i * 8;
            if (m >= MROWS) continue;
            int b = m & 31, t = m >> 5;
            float* orow = out + (size_t)(b * TT + t + 1) * VOC;
#pragma unroll
            for (int ni = 0; ni < 4; ni++) {
                int n = n0 + wn + ni * 8 + cbase;
                float2 v;
                v.x = c[mi][ni][half2i * 2 + 0] + b2[n];
                v.y = c[mi][ni][half2i * 2 + 1] + b2[n + 1];
                *(float2*)(orow + n) = v;
            }
        }
    }
}

// ================================ host ================================
extern "C" void kernel_launch(void* const* d_in, const int* in_sizes, int n_in,
                              void* d_out, int out_size) {
    const int*   src       = (const int*)  d_in[0];
    const int*   trg       = (const int*)  d_in[1];
    const int*   src_lens  = (const int*)  d_in[2];
    const float* enc_embed = (const float*)d_in[3];
    const float* Wi_f      = (const float*)d_in[4];
    const float* Wh_f      = (const float*)d_in[5];
    const float* bi_f      = (const float*)d_in[6];
    const float* bh_f      = (const float*)d_in[7];
    const float* Wi_b      = (const float*)d_in[8];
    const float* Wh_b      = (const float*)d_in[9];
    const float* bi_b      = (const float*)d_in[10];
    const float* bh_b      = (const float*)d_in[11];
    const float* W_e2d     = (const float*)d_in[12];
    const float* b_e2d     = (const float*)d_in[13];
    const float* dec_embed = (const float*)d_in[14];
    const float* Wi_d      = (const float*)d_in[15];
    const float* Wh_d      = (const float*)d_in[16];
    const float* bi_d      = (const float*)d_in[17];
    const float* bh_d      = (const float*)d_in[18];
    const float* Wq        = (const float*)d_in[19];
    const float* bq        = (const float*)d_in[20];
    const float* Wk        = (const float*)d_in[21];
    const float* bk        = (const float*)d_in[22];
    const float* Wv        = (const float*)d_in[23];
    const float* bv        = (const float*)d_in[24];
    const float* W1        = (const float*)d_in[25];
    const float* b1        = (const float*)d_in[26];
    const float* W2        = (const float*)d_in[27];
    const float* b2        = (const float*)d_in[28];
    float* out = (float*)d_out;

    float* scr = nullptr;
    cudaGetSymbolAddress((void**)&scr, g_scr);
    __half* xh = nullptr;
    cudaGetSymbolAddress((void**)&xh, g_xh);
    __half* w2h = nullptr;
    cudaGetSymbolAddress((void**)&w2h, g_w2h);

    float* p_emb  = scr;
    float* p_gif  = p_emb  + NF_EMB;
    float* p_gib  = p_gif  + NF_GI;
    float* p_wr   = p_gib  + NF_GI;
    float* p_henc = p_wr   + NF_WR;
    float* p_K    = p_henc + NF_HENC;
    float* p_V    = p_K    + NF_K;
    float* p_demb = p_V    + NF_V;
    float* p_gid  = p_demb + NF_DEMB;
    float* p_hdec = p_gid  + NF_GID;
    float* p_hid  = p_hdec + NF_HDEC;
    float* p_whTe = p_hid  + NF_HID;
    float* p_whTd = p_whTe + NF_WHTE;
    float* p_hgru = p_whTd + NF_WHTD;

    static cudaStream_t s2;
    static cudaEvent_t evFork, evPack, evGid, evD[3], evJoin;
    static int once = 0;
    if (!once) {
        cudaFuncSetAttribute(enc_persist, cudaFuncAttributeMaxDynamicSharedMemorySize, RSMEM2);
        cudaFuncSetAttribute(dec_persist, cudaFuncAttributeMaxDynamicSharedMemorySize, RSMEM2);
        cudaStreamCreateWithFlags(&s2, cudaStreamNonBlocking);
        cudaEventCreateWithFlags(&evFork, cudaEventDisableTiming);
        cudaEventCreateWithFlags(&evPack, cudaEventDisableTiming);
        cudaEventCreateWithFlags(&evGid,  cudaEventDisableTiming);
        for (int i = 0; i < 3; i++) cudaEventCreateWithFlags(&evD[i], cudaEventDisableTiming);
        cudaEventCreateWithFlags(&evJoin, cudaEventDisableTiming);
        once = 1;
    }

    // 0) init on main stream, then fork s2
    init_zero<<<(BB * VOC + 255) / 256, 256>>>(out, p_henc);
    cudaEventRecord(evFork, 0);
    cudaStreamWaitEvent(s2, evFork, 0);

    // ---- s2 branch: weight prep + decoder input projections ----
    transpose_w2<<<dim3(VOC / 32, DD / 32), dim3(32, 8), 0, s2>>>(W2, w2h);
    pack_whT<<<(512 * 512 + 255) / 256, 256, 0, s2>>>(Wh_f, Wh_b, Wh_d, p_whTe, p_whTd);
    cudaEventRecord(evPack, s2);
    gather_trg<<<(BB * (TT - 1) * (EE / 4) + 255) / 256, 256, 0, s2>>>(trg, dec_embed, p_demb);
    gemm_k<0,0><<<dim3(G3 / 64, (BB * (TT - 1) + 63) / 64), 256, 0, s2>>>(
        p_demb, Wi_d, bi_d, p_gid, BB * (TT - 1), G3, EE);
    cudaEventRecord(evGid, s2);

    // ---- main stream: encoder path ----
    gather_src<<<(BB * SS * (EE / 4) + 255) / 256, 256>>>(src, enc_embed, p_emb);
    gemm_k<0,0><<<dim3(G3 / 64, (BB * SS) / 64), 256>>>(p_emb, Wi_f, bi_f, p_gif, BB * SS, G3, EE);
    gemm_k<0,0><<<dim3(G3 / 64, (BB * SS) / 64), 256>>>(p_emb, Wi_b, bi_b, p_gib, BB * SS, G3, EE);
    cudaStreamWaitEvent(0, evPack, 0);
    enc_persist<<<128, 256, RSMEM2>>>(p_whTe, bh_f, bh_b, src_lens, p_gif, p_gib, p_henc, p_wr);
    float* p_sent = p_henc;

    gemm_k<0,0><<<dim3(KKQ / 64, (BB * SS) / 64), 256>>>(p_wr, Wk, bk, p_K, BB * SS, KKQ, 2 * HH);
    gemm_k<0,0><<<dim3(DD / 64, (BB * SS) / 64), 256>>>(p_wr, Wv, bv, p_V, BB * SS, DD, 2 * HH);
    gemm_k<1,0><<<dim3(DD / 64, 1), 256>>>(p_sent, W_e2d, b_e2d, p_hdec, BB, DD, 2 * HH);

    cudaStreamWaitEvent(0, evGid, 0);

    // ---- 4-way decoder/head pipeline (R11 chunking: 16/16/16/15) ----
    for (int c = 0; c < 4; c++) {
        int t0 = c * 16;
        int t1 = (c == 3) ? (TT - 1) : (c * 16 + 16);
        dec_persist<<<64, 256, RSMEM2>>>(p_whTd, bh_d, p_gid, Wq, bq, p_K, p_V,
                                         p_hdec, p_hid, p_hgru, t0, t1, 4 + c);
        int m0 = c * 512;
        int mrows = (c == 3) ? (MROWS - m0) : 512;
        if (c < 3) {
            cudaEventRecord(evD[c], 0);
            cudaStreamWaitEvent(s2, evD[c], 0);
            gemm_k<1,1><<<dim3(DD / 64, 8), 256, 0, s2>>>(
                p_hid + (size_t)m0 * DD, W1, b1, xh + (size_t)m0 * DD, mrows, DD, DD);
            head_mma<<<dim3(4, VOC / 128), 256, 0, s2>>>(xh, w2h, b2, out, c * 4);
            if (c == 2) cudaEventRecord(evJoin, s2);
        } else {
            gemm_k<1,1><<<dim3(DD / 64, 8), 256>>>(
                p_hid + (size_t)m0 * DD, W1, b1, xh + (size_t)m0 * DD, mrows, DD, DD);
            head_mma<<<dim3(4, VOC / 128), 256>>>(xh, w2h, b2, out, 12);
        }
    }

    // join s2
    cudaStreamWaitEvent(0, evJoin, 0);
}

// round 14
// speedup vs baseline: 1.0192x; 1.0165x over previous
#include <cuda_runtime.h>
#include <cuda_fp16.h>
#include <cstdint>
#include <math.h>

#define BB   32
#define SS   64
#define TT   64
#define EE   256
#define HH   512
#define DD   512
#define KKQ  64
#define VOC  32000
#define G3   1536
#define MROWS (BB*(TT-1))   // 2016

#define NF_EMB   (BB*SS*EE)
#define NF_GI    (BB*SS*G3)
#define NF_WR    (BB*SS*2*HH)
#define NF_HENC  (2*BB*2*HH)
#define NF_K     (BB*SS*KKQ)
#define NF_V     (BB*SS*DD)
#define NF_DEMB  (BB*(TT-1)*EE)
#define NF_GID   (BB*(TT-1)*G3)
#define NF_HDEC  (BB*DD)
#define NF_HID   (BB*(TT-1)*DD)
#define NF_WHTE  (2*512*1536)
#define NF_WHTD  (512*1536)
#define NF_HGRU  (BB*DD)

#define NF_TOTAL (NF_EMB + 2*NF_GI + NF_WR + NF_HENC + NF_K + NF_V + NF_DEMB + NF_GID + \
                  NF_HDEC + NF_HID + NF_WHTE + NF_WHTD + NF_HGRU)

__device__ float g_scr[NF_TOTAL];
__device__ __half g_xh[MROWS * DD];
__device__ __half g_w2h[VOC * DD];
__device__ unsigned g_bars[8];   // 0..3 enc (dir,bg) groups; 4..7 dec chunks

__device__ __forceinline__ float sigm(float x) { return 1.0f / (1.0f + expf(-x)); }
__device__ __forceinline__ float gelu_f(float x) { return 0.5f * x * (1.0f + erff(x * 0.7071067811865475f)); }

__device__ __forceinline__ float ldcg1(const float* p) {
    float v; asm volatile("ld.global.cg.f32 %0, [%1];" : "=f"(v) : "l"(p)); return v;
}
__device__ __forceinline__ float4 ldcg4(const float* p) {
    float4 v;
    asm volatile("ld.global.cg.v4.f32 {%0,%1,%2,%3}, [%4];"
                 : "=f"(v.x), "=f"(v.y), "=f"(v.z), "=f"(v.w) : "l"(p));
    return v;
}

__device__ __forceinline__ void ffma2(unsigned long long& d,
                                      unsigned long long a, unsigned long long b) {
    asm("fma.rn.f32x2 %0, %1, %2, %0;" : "+l"(d) : "l"(a), "l"(b));
}
__device__ __forceinline__ unsigned long long splat2(float a) {
    unsigned long long r;
    asm("mov.b64 %0, {%1, %1};" : "=l"(r) : "f"(a));
    return r;
}
__device__ __forceinline__ float hsum2(unsigned long long v) {
    float lo = __uint_as_float((unsigned)(v & 0xffffffffull));
    float hi = __uint_as_float((unsigned)(v >> 32));
    return lo + hi;
}
__device__ __forceinline__ float lane0(unsigned long long v) {
    return __uint_as_float((unsigned)(v & 0xffffffffull));
}
__device__ __forceinline__ float lane1(unsigned long long v) {
    return __uint_as_float((unsigned)(v >> 32));
}

__device__ __forceinline__ void gsync(unsigned* bar, unsigned& epoch, unsigned nb) {
    __syncthreads();
    if (threadIdx.x == 0) {
        epoch += nb;
        __threadfence();
        atomicAdd(bar, 1u);
        while (*(volatile unsigned*)bar < epoch) __nanosleep(32);
        __threadfence();
    }
    __syncthreads();
}

// ---------------- init ----------------
__global__ void init_zero(float* __restrict__ out, float* __restrict__ henc) {
    int i = blockIdx.x * blockDim.x + threadIdx.x;
    if (i < 8) g_bars[i] = 0;
    if (i < BB * VOC) {
        int b = i / VOC;
        out[(size_t)b * TT * VOC + (i % VOC)] = 0.0f;
    }
    if (i < NF_HENC) henc[i] = 0.0f;
}

// ---------------- embedding gathers ----------------
__global__ void gather_src(const int* __restrict__ src, const float* __restrict__ tab,
                           float* __restrict__ emb) {
    int i = blockIdx.x * blockDim.x + threadIdx.x;
    if (i >= BB * SS * (EE / 4)) return;
    int row = i / (EE / 4);
    int c   = i % (EE / 4);
    ((float4*)emb)[row * (EE / 4) + c] =
        ((const float4*)tab)[(size_t)src[row] * (EE / 4) + c];
}

__global__ void gather_trg(const int* __restrict__ trg, const float* __restrict__ tab,
                           float* __restrict__ demb) {
    int i = blockIdx.x * blockDim.x + threadIdx.x;
    if (i >= BB * (TT - 1) * (EE / 4)) return;
    int m = i / (EE / 4);
    int c = i % (EE / 4);
    int t = m / BB, b = m % BB;
    int tok = trg[b * TT + t];
    ((float4*)demb)[m * (EE / 4) + c] =
        ((const float4*)tab)[(size_t)tok * (EE / 4) + c];
}

// ---------------- transpose-pack recurrent weights: [dir][j][gate][k] ----------------
__global__ void pack_whT(const float* __restrict__ Wh_f, const float* __restrict__ Wh_b,
                         const float* __restrict__ Wh_d,
                         float* __restrict__ whTe, float* __restrict__ whTd) {
    int idx = blockIdx.x * blockDim.x + threadIdx.x;
    if (idx >= 512 * 512) return;
    int k = idx >> 9, j = idx & 511;
#pragma unroll
    for (int g = 0; g < 3; g++) {
        whTe[(size_t)(j * 3 + g) * 512 + k] = Wh_f[k * G3 + g * 512 + j];
        whTe[(size_t)512 * 1536 + (j * 3 + g) * 512 + k] = Wh_b[k * G3 + g * 512 + j];
        whTd[(size_t)(j * 3 + g) * 512 + k] = Wh_d[k * G3 + g * 512 + j];
    }
}

// ---------------- generic fp32 GEMM (f32x2 inner loop) ----------------
template<int GELU, int OUT16>
__global__ void gemm_k(const float* __restrict__ A, const float* __restrict__ Bm,
                       const float* __restrict__ bias, void* __restrict__ Cv,
                       int M, int N, int K) {
    __shared__ float As[16][68];
    __shared__ float Bs[16][68];
    int tid = threadIdx.x;
    int m0 = blockIdx.y * 64, n0 = blockIdx.x * 64;
    int tx = tid & 15, ty = tid >> 4;

    unsigned long long acc2[4][2];
#pragma unroll
    for (int i = 0; i < 4; i++) { acc2[i][0] = 0ull; acc2[i][1] = 0ull; }

    int lam = tid >> 2;
    int lak = (tid & 3) * 4;
    int lbk = tid >> 4;
    int lbn = (tid & 15) * 4;

    for (int k0 = 0; k0 < K; k0 += 16) {
        float4 av = (m0 + lam < M)
            ? *(const float4*)&A[(size_t)(m0 + lam) * K + k0 + lak]
            : make_float4(0.f, 0.f, 0.f, 0.f);
        float4 bv = *(const float4*)&Bm[(size_t)(k0 + lbk) * N + n0 + lbn];
        __syncthreads();
        As[lak + 0][lam] = av.x;
        As[lak + 1][lam] = av.y;
        As[lak + 2][lam] = av.z;
        As[lak + 3][lam] = av.w;
        *(float4*)&Bs[lbk][lbn] = bv;
        __syncthreads();
#pragma unroll
        for (int kk = 0; kk < 16; kk++) {
            float4 a4 = *(const float4*)&As[kk][ty * 4];
            unsigned long long b0 = *(const unsigned long long*)&Bs[kk][tx * 4];
            unsigned long long b1 = *(const unsigned long long*)&Bs[kk][tx * 4 + 2];
            unsigned long long s0 = splat2(a4.x);
            unsigned long long s1 = splat2(a4.y);
            unsigned long long s2 = splat2(a4.z);
            unsigned long long s3 = splat2(a4.w);
            ffma2(acc2[0][0], s0, b0); ffma2(acc2[0][1], s0, b1);
            ffma2(acc2[1][0], s1, b0); ffma2(acc2[1][1], s1, b1);
            ffma2(acc2[2][0], s2, b0); ffma2(acc2[2][1], s2, b1);
            ffma2(acc2[3][0], s3, b0); ffma2(acc2[3][1], s3, b1);
        }
    }

#pragma unroll
    for (int i = 0; i < 4; i++) {
        int m = m0 + ty * 4 + i;
        if (m >= M) continue;
        float vj[4] = { lane0(acc2[i][0]), lane1(acc2[i][0]),
                        lane0(acc2[i][1]), lane1(acc2[i][1]) };
#pragma unroll
        for (int j = 0; j < 4; j++) {
            int n = n0 + tx * 4 + j;
            float v = vj[j] + bias[n];
            if (GELU) v = gelu_f(v);
            if (OUT16) ((__half*)Cv)[(size_t)m * N + n] = __float2half(v);
            else       ((float*)Cv)[(size_t)m * N + n] = v;
        }
    }
}

// ===== recurrence smem layout =====
#define WP2   1538
#define HP2   516
#define OFF_H   (16 * WP2)
#define OFF_P   (16 * WP2 + 16 * HP2)
#define RSMEM2  ((16 * WP2 + 16 * HP2 + 16 * 3 * 16 * 16) * 4)   // 180608 B

__device__ __forceinline__ void fill_wslab(float* ws, const float* wsrc, int tid) {
#pragma unroll
    for (int u = 0; u < 24; u++) {
        int idx4 = u * 256 + tid;
        int jl = idx4 / 384;
        int off = (idx4 - jl * 384) * 4;
        float4 v = *(const float4*)&wsrc[(size_t)jl * 1536 + off];
        float* d = &ws[jl * WP2 + off];
        *(float2*)d = make_float2(v.x, v.y);
        *(float2*)(d + 2) = make_float2(v.z, v.w);
    }
}

__device__ __forceinline__ void gru_core(const float* ws, const float* hsf,
                                         float* part, int tx, int ty) {
    unsigned long long acc[16][3];
#pragma unroll
    for (int b = 0; b < 16; b++)
#pragma unroll
        for (int g = 0; g < 3; g++) acc[b][g] = 0ull;

    const float* wr_p = ws + tx * WP2 + ty * 32;
    const float* wz_p = wr_p + 512;
    const float* wn_p = wr_p + 1024;
    const float* h_p  = hsf + ty * 32;

#pragma unroll
    for (int kk2 = 0; kk2 < 16; kk2++) {
        unsigned long long wr = *(const unsigned long long*)(wr_p + kk2 * 2);
        unsigned long long wz = *(const unsigned long long*)(wz_p + kk2 * 2);
        unsigned long long wn = *(const unsigned long long*)(wn_p + kk2 * 2);
#pragma unroll
        for (int b = 0; b < 16; b++) {
            unsigned long long h2 = *(const unsigned long long*)(h_p + b * HP2 + kk2 * 2);
            ffma2(acc[b][0], h2, wr);
            ffma2(acc[b][1], h2, wz);
            ffma2(acc[b][2], h2, wn);
        }
    }
#pragma unroll
    for (int b = 0; b < 16; b++)
#pragma unroll
        for (int g = 0; g < 3; g++)
            part[((b * 3 + g) * 16 + ty) * 16 + tx] = hsum2(acc[b][g]);
}

// ================= persistent encoder: 4 independent (dir,bg) barrier groups =================
__global__ void __launch_bounds__(256, 1)
enc_persist(const float* __restrict__ whTe,
            const float* __restrict__ bh_f, const float* __restrict__ bh_b,
            const int* __restrict__ src_lens,
            const float* __restrict__ gi_f, const float* __restrict__ gi_b,
            float* __restrict__ henc, float* __restrict__ wr_out) {
    extern __shared__ float smem[];
    float* ws   = smem;
    float* hsf  = smem + OFF_H;
    float* part = smem + OFF_P;

    int cta = blockIdx.x;
    int dir = cta & 1, bg = (cta >> 1) & 1, jt = cta >> 2;
    unsigned* bar = &g_bars[cta & 3];
    int tid = threadIdx.x;
    int tx = tid & 15, ty = tid >> 4;
    const float* bh = dir ? bh_b : bh_f;
    const float* gi = dir ? gi_b : gi_f;

    fill_wslab(ws, whTe + (size_t)dir * 512 * 1536 + (size_t)jt * 16 * 1536, tid);

    int j_g = jt * 16 + tx;
    int b_g = bg * 16 + ty;
    float br = bh[j_g], bz = bh[512 + j_g], bn = bh[1024 + j_g];
    int len = max(src_lens[b_g], 1);
    unsigned epoch = 0;
    __syncthreads();

    for (int step = 0; step < SS; step++) {
        int t = dir ? (SS - 1 - step) : step;
        int p = step & 1;
        const float* hin = henc + p * (BB * 1024);
        float* hout = henc + (p ^ 1) * (BB * 1024);

#pragma unroll
        for (int u = 0; u < 8; u++) {
            int idx = u * 256 + tid;
            int bl = idx >> 7, kq = idx & 127;
            float4 h4 = ldcg4(&hin[(bg * 16 + bl) * 1024 + dir * 512 + kq * 4]);
            *(float4*)&hsf[bl * HP2 + kq * 4] = h4;
        }
        __syncthreads();

        gru_core(ws, hsf, part, tx, ty);
        __syncthreads();

        {
            float sr = 0.f, sz = 0.f, sn = 0.f;
#pragma unroll
            for (int s = 0; s < 16; s++) {
                sr += part[((ty * 3 + 0) * 16 + s) * 16 + tx];
                sz += part[((ty * 3 + 1) * 16 + s) * 16 + tx];
                sn += part[((ty * 3 + 2) * 16 + s) * 16 + tx];
            }
            size_t row = (size_t)(b_g * SS + t);
            float gir = gi[row * G3 + j_g];
            float giz = gi[row * G3 + 512 + j_g];
            float gin = gi[row * G3 + 1024 + j_g];
            float hold = hsf[ty * HP2 + j_g];
            float r = sigm(gir + sr + br);
            float z = sigm(giz + sz + bz);
            float n = tanhf(gin + r * (sn + bn));
            float hnew = (1.0f - z) * n + z * hold;
            bool valid = t < len;
            hout[b_g * 1024 + dir * 512 + j_g] = valid ? hnew : hold;
            wr_out[row * 1024 + dir * 512 + j_g] = valid ? hnew : 0.0f;
        }
        gsync(bar, epoch, 32);
    }
}

// ================= persistent decoder (t-range chunk, own barrier counter) =================
__global__ void __launch_bounds__(256, 1)
dec_persist(const float* __restrict__ whTd, const float* __restrict__ bh,
            const float* __restrict__ gi,
            const float* __restrict__ Wq, const float* __restrict__ bq,
            const float* __restrict__ Kmat, const float* __restrict__ Vmat,
            float* __restrict__ hdec, float* __restrict__ hid_all,
            float* __restrict__ hgru, int t0, int t1, int bar_idx) {
    extern __shared__ float smem[];
    float* ws   = smem;
    float* hsf  = smem + OFF_H;
    float* part = smem + OFF_P;
    __shared__ float hsh[DD];
    __shared__ float qsh[KKQ];
    __shared__ float ssh[SS];
    __shared__ float red[256];

    int cta = blockIdx.x;
    int bg = cta & 1, jt = cta >> 1;
    int tid = threadIdx.x;
    int tx = tid & 15, ty = tid >> 4;
    unsigned* bar = &g_bars[bar_idx];

    fill_wslab(ws, whTd + (size_t)jt * 16 * 1536, tid);

    int j_g = jt * 16 + tx;
    int b_g = bg * 16 + ty;
    float br = bh[j_g], bz = bh[512 + j_g], bn = bh[1024 + j_g];
    unsigned epoch = 0;
    __syncthreads();

    for (int t = t0; t < t1; t++) {
#pragma unroll
        for (int u = 0; u < 4; u++) {
            int idx = u * 256 + tid;
            int bl = idx >> 6, kq = idx & 63;
            float4 h4 = ldcg4(&hdec[(bg * 16 + bl) * 512 + kq * 8]);
            float4 h4b = ldcg4(&hdec[(bg * 16 + bl) * 512 + kq * 8 + 4]);
            *(float4*)&hsf[bl * HP2 + kq * 8] = h4;
            *(float4*)&hsf[bl * HP2 + kq * 8 + 4] = h4b;
        }
        __syncthreads();

        gru_core(ws, hsf, part, tx, ty);
        __syncthreads();

        {
            float sr = 0.f, sz = 0.f, sn = 0.f;
#pragma unroll
            for (int s = 0; s < 16; s++) {
                sr += part[((ty * 3 + 0) * 16 + s) * 16 + tx];
                sz += part[((ty * 3 + 1) * 16 + s) * 16 + tx];
                sn += part[((ty * 3 + 2) * 16 + s) * 16 + tx];
            }
            size_t row = (size_t)(t * BB + b_g);
            float gir = gi[row * G3 + j_g];
            float giz = gi[row * G3 + 512 + j_g];
            float gin = gi[row * G3 + 1024 + j_g];
            float hold = hsf[ty * HP2 + j_g];
            float r = sigm(gir + sr + br);
            float z = sigm(giz + sz + bz);
            float n = tanhf(gin + r * (sn + bn));
            hgru[b_g * 512 + j_g] = (1.0f - z) * n + z * hold;
        }
        gsync(bar, epoch, gridDim.x);

        if (cta < BB) {
            int ba = cta;
            size_t rowa = (size_t)(t * BB + ba);
            for (int i = tid; i < DD; i += 256) hsh[i] = ldcg1(&hgru[ba * 512 + i]);
            __syncthreads();
            {
                int jq = tid & 63, prt = tid >> 6;
                float acc = 0.f;
                int kb = prt * 128;
                for (int k = kb; k < kb + 128; k++) acc = fmaf(hsh[k], Wq[k * KKQ + jq], acc);
                red[tid] = acc;
            }
            __syncthreads();
            if (tid < KKQ) {
                float q = red[tid] + red[tid + 64] + red[tid + 128] + red[tid + 192] + bq[tid];
                qsh[tid] = q * 0.125f;
            }
            __syncthreads();
            if (tid < SS) {
                const float* Kp = Kmat + (size_t)(ba * SS + tid) * KKQ;
                float sc = 0.f;
                for (int k = 0; k < KKQ; k++) sc = fmaf(qsh[k], Kp[k], sc);
                ssh[tid] = sc;
            }
            __syncthreads();
            if (tid == 0) {
                float m = ssh[0];
                for (int s = 1; s < SS; s++) m = fmaxf(m, ssh[s]);
                float sum = 0.f;
                for (int s = 0; s < SS; s++) { float e = expf(ssh[s] - m); ssh[s] = e; sum += e; }
                red[0] = 1.0f / sum;
            }
            __syncthreads();
            float inv = red[0];
            __syncthreads();
            if (tid < SS) ssh[tid] *= inv;
            __syncthreads();
            for (int d0 = tid; d0 < DD; d0 += 256) {
                float a = 0.f;
                for (int s = 0; s < SS; s++)
                    a = fmaf(ssh[s], Vmat[(size_t)(ba * SS + s) * DD + d0], a);
                float hid = hsh[d0] + a;
                hdec[ba * 512 + d0] = hid;
                hid_all[rowa * 512 + d0] = hid;
            }
        }
        gsync(bar, epoch, gridDim.x);
    }
}

// transpose W2 [K=512, N=32000] fp32 -> W2h [N, K] fp16
__global__ void transpose_w2(const float* __restrict__ W2, __half* __restrict__ W2h) {
    __shared__ float ts[32][33];
    int n0 = blockIdx.x * 32;
    int k0 = blockIdx.y * 32;
    int tx = threadIdx.x, ty = threadIdx.y;
#pragma unroll
    for (int j = 0; j < 4; j++)
        ts[ty + j * 8][tx] = W2[(size_t)(k0 + ty + j * 8) * VOC + n0 + tx];
    __syncthreads();
#pragma unroll
    for (int j = 0; j < 4; j++) {
        int n = n0 + ty + j * 8;
        int k = k0 + tx;
        W2h[(size_t)n * DD + k] = __float2half(ts[tx][ty + j * 8]);
    }
}

// ================= HMMA fp16 head GEMM (m-tile offset) =================
#define HPITCH 72

__device__ __forceinline__ uint32_t smem_u32(const void* p) {
    uint32_t a;
    asm("{ .reg .u64 t; cvta.to.shared.u64 t, %1; cvt.u32.u64 %0, t; }" : "=r"(a) : "l"(p));
    return a;
}
__device__ __forceinline__ void ldmatrix_x4(uint32_t* r, uint32_t addr) {
    asm volatile("ldmatrix.sync.aligned.m8n8.x4.shared.b16 {%0,%1,%2,%3}, [%4];"
                 : "=r"(r[0]), "=r"(r[1]), "=r"(r[2]), "=r"(r[3]) : "r"(addr));
}
__device__ __forceinline__ void ldmatrix_x2(uint32_t* r, uint32_t addr) {
    asm volatile("ldmatrix.sync.aligned.m8n8.x2.shared.b16 {%0,%1}, [%2];"
                 : "=r"(r[0]), "=r"(r[1]) : "r"(addr));
}
__device__ __forceinline__ void mma16816(float* c, const uint32_t* a, const uint32_t* b) {
    asm volatile(
        "mma.sync.aligned.m16n8k16.row.col.f32.f16.f16.f32 "
        "{%0,%1,%2,%3}, {%4,%5,%6,%7}, {%8,%9}, {%0,%1,%2,%3};"
        : "+f"(c[0]), "+f"(c[1]), "+f"(c[2]), "+f"(c[3])
        : "r"(a[0]), "r"(a[1]), "r"(a[2]), "r"(a[3]), "r"(b[0]), "r"(b[1]));
}

__global__ void __launch_bounds__(256, 2)
head_mma(const __half* __restrict__ Xh, const __half* __restrict__ W2h,
         const float* __restrict__ b2, float* __restrict__ out, int moff) {
    __shared__ __half As[128 * HPITCH];
    __shared__ __half Bs[128 * HPITCH];

    int tid = threadIdx.x;
    int wid = tid >> 5, lane = tid & 31;
    int m0 = (blockIdx.x + moff) * 128;
    int n0 = blockIdx.y * 128;
    int wm = (wid >> 2) * 64;
    int wn = (wid & 3) * 32;

    float c[4][4][4];
#pragma unroll
    for (int mi = 0; mi < 4; mi++)
#pragma unroll
        for (int ni = 0; ni < 4; ni++)
#pragma unroll
            for (int q = 0; q < 4; q++) c[mi][ni][q] = 0.0f;

    uint32_t as_base = smem_u32(As);
    uint32_t bs_base = smem_u32(Bs);

    for (int kc = 0; kc < 8; kc++) {
        int k0 = kc * 64;
        __syncthreads();
#pragma unroll
        for (int it = 0; it < 4; it++) {
            int idx = it * 256 + tid;
            int row = idx >> 3;
            int col = (idx & 7) * 8;
            uint4 va = (m0 + row < MROWS)
                ? *(const uint4*)(Xh + (size_t)(m0 + row) * DD + k0 + col)
                : make_uint4(0, 0, 0, 0);
            *(uint4*)(As + row * HPITCH + col) = va;
            uint4 vb = *(const uint4*)(W2h + (size_t)(n0 + row) * DD + k0 + col);
            *(uint4*)(Bs + row * HPITCH + col) = vb;
        }
        __syncthreads();

#pragma unroll
        for (int k16 = 0; k16 < 4; k16++) {
            uint32_t afrag[4][4], bfrag[4][2];
#pragma unroll
            for (int mi = 0; mi < 4; mi++) {
                int r = wm + mi * 16 + (lane & 15);
                int cl = k16 * 16 + ((lane >> 4) * 8);
                ldmatrix_x4(afrag[mi], as_base + (uint32_t)(r * HPITCH + cl) * 2);
            }
#pragma unroll
            for (int ni = 0; ni < 4; ni++) {
                int r = wn + ni * 8 + (lane & 7);
                int cl = k16 * 16 + (((lane >> 3) & 1) * 8);
                ldmatrix_x2(bfrag[ni], bs_base + (uint32_t)(r * HPITCH + cl) * 2);
            }
#pragma unroll
            for (int mi = 0; mi < 4; mi++)
#pragma unroll
                for (int ni = 0; ni < 4; ni++)
                    mma16816(c[mi][ni], afrag[mi], bfrag[ni]);
        }
    }

    int rbase = lane >> 2;
    int cbase = (lane & 3) * 2;
#pragma unroll
    for (int mi = 0; mi < 4; mi++) {
#pragma unroll
        for (int half2i = 0; half2i < 2; half2i++) {
            int m = m0 + wm + mi * 16 + rbase + half2i * 8;
            if (m >= MROWS) continue;
            int b = m & 31, t = m >> 5;
            float* orow = out + (size_t)(b * TT + t + 1) * VOC;
#pragma unroll
            for (int ni = 0; ni < 4; ni++) {
                int n = n0 + wn + ni * 8 + cbase;
                float2 v;
                v.x = c[mi][ni][half2i * 2 + 0] + b2[n];
                v.y = c[mi][ni][half2i * 2 + 1] + b2[n + 1];
                *(float2*)(orow + n) = v;
            }
        }
    }
}

// ================================ host ================================
extern "C" void kernel_launch(void* const* d_in, const int* in_sizes, int n_in,
                              void* d_out, int out_size) {
    const int*   src       = (const int*)  d_in[0];
    const int*   trg       = (const int*)  d_in[1];
    const int*   src_lens  = (const int*)  d_in[2];
    const float* enc_embed = (const float*)d_in[3];
    const float* Wi_f      = (const float*)d_in[4];
    const float* Wh_f      = (const float*)d_in[5];
    const float* bi_f      = (const float*)d_in[6];
    const float* bh_f      = (const float*)d_in[7];
    const float* Wi_b      = (const float*)d_in[8];
    const float* Wh_b      = (const float*)d_in[9];
    const float* bi_b      = (const float*)d_in[10];
    const float* bh_b      = (const float*)d_in[11];
    const float* W_e2d     = (const float*)d_in[12];
    const float* b_e2d     = (const float*)d_in[13];
    const float* dec_embed = (const float*)d_in[14];
    const float* Wi_d      = (const float*)d_in[15];
    const float* Wh_d      = (const float*)d_in[16];
    const float* bi_d      = (const float*)d_in[17];
    const float* bh_d      = (const float*)d_in[18];
    const float* Wq        = (const float*)d_in[19];
    const float* bq        = (const float*)d_in[20];
    const float* Wk        = (const float*)d_in[21];
    const float* bk        = (const float*)d_in[22];
    const float* Wv        = (const float*)d_in[23];
    const float* bv        = (const float*)d_in[24];
    const float* W1        = (const float*)d_in[25];
    const float* b1        = (const float*)d_in[26];
    const float* W2        = (const float*)d_in[27];
    const float* b2        = (const float*)d_in[28];
    float* out = (float*)d_out;

    float* scr = nullptr;
    cudaGetSymbolAddress((void**)&scr, g_scr);
    __half* xh = nullptr;
    cudaGetSymbolAddress((void**)&xh, g_xh);
    __half* w2h = nullptr;
    cudaGetSymbolAddress((void**)&w2h, g_w2h);

    float* p_emb  = scr;
    float* p_gif  = p_emb  + NF_EMB;
    float* p_gib  = p_gif  + NF_GI;
    float* p_wr   = p_gib  + NF_GI;
    float* p_henc = p_wr   + NF_WR;
    float* p_K    = p_henc + NF_HENC;
    float* p_V    = p_K    + NF_K;
    float* p_demb = p_V    + NF_V;
    float* p_gid  = p_demb + NF_DEMB;
    float* p_hdec = p_gid  + NF_GID;
    float* p_hid  = p_hdec + NF_HDEC;
    float* p_whTe = p_hid  + NF_HID;
    float* p_whTd = p_whTe + NF_WHTE;
    float* p_hgru = p_whTd + NF_WHTD;

    static cudaStream_t s2;
    static cudaEvent_t evFork, evPack, evGid, evD[3], evJoin;
    static int once = 0;
    if (!once) {
        cudaFuncSetAttribute(enc_persist, cudaFuncAttributeMaxDynamicSharedMemorySize, RSMEM2);
        cudaFuncSetAttribute(dec_persist, cudaFuncAttributeMaxDynamicSharedMemorySize, RSMEM2);
        cudaStreamCreateWithFlags(&s2, cudaStreamNonBlocking);
        cudaEventCreateWithFlags(&evFork, cudaEventDisableTiming);
        cudaEventCreateWithFlags(&evPack, cudaEventDisableTiming);
        cudaEventCreateWithFlags(&evGid,  cudaEventDisableTiming);
        for (int i = 0; i < 3; i++) cudaEventCreateWithFlags(&evD[i], cudaEventDisableTiming);
        cudaEventCreateWithFlags(&evJoin, cudaEventDisableTiming);
        once = 1;
    }

    // 0) init on main stream, then fork s2
    init_zero<<<(BB * VOC + 255) / 256, 256>>>(out, p_henc);
    cudaEventRecord(evFork, 0);
    cudaStreamWaitEvent(s2, evFork, 0);

    // ---- s2 branch: weight prep + decoder input projections ----
    transpose_w2<<<dim3(VOC / 32, DD / 32), dim3(32, 8), 0, s2>>>(W2, w2h);
    pack_whT<<<(512 * 512 + 255) / 256, 256, 0, s2>>>(Wh_f, Wh_b, Wh_d, p_whTe, p_whTd);
    cudaEventRecord(evPack, s2);
    gather_trg<<<(BB * (TT - 1) * (EE / 4) + 255) / 256, 256, 0, s2>>>(trg, dec_embed, p_demb);
    gemm_k<0,0><<<dim3(G3 / 64, (BB * (TT - 1) + 63) / 64), 256, 0, s2>>>(
        p_demb, Wi_d, bi_d, p_gid, BB * (TT - 1), G3, EE);
    cudaEventRecord(evGid, s2);

    // ---- main stream: encoder path ----
    gather_src<<<(BB * SS * (EE / 4) + 255) / 256, 256>>>(src, enc_embed, p_emb);
    gemm_k<0,0><<<dim3(G3 / 64, (BB * SS) / 64), 256>>>(p_emb, Wi_f, bi_f, p_gif, BB * SS, G3, EE);
    gemm_k<0,0><<<dim3(G3 / 64, (BB * SS) / 64), 256>>>(p_emb, Wi_b, bi_b, p_gib, BB * SS, G3, EE);
    cudaStreamWaitEvent(0, evPack, 0);
    enc_persist<<<128, 256, RSMEM2>>>(p_whTe, bh_f, bh_b, src_lens, p_gif, p_gib, p_henc, p_wr);
    float* p_sent = p_henc;

    gemm_k<0,0><<<dim3(KKQ / 64, (BB * SS) / 64), 256>>>(p_wr, Wk, bk, p_K, BB * SS, KKQ, 2 * HH);
    gemm_k<0,0><<<dim3(DD / 64, (BB * SS) / 64), 256>>>(p_wr, Wv, bv, p_V, BB * SS, DD, 2 * HH);
    gemm_k<1,0><<<dim3(DD / 64, 1), 256>>>(p_sent, W_e2d, b_e2d, p_hdec, BB, DD, 2 * HH);

    cudaStreamWaitEvent(0, evGid, 0);

    // ---- 4-way decoder/head pipeline (16/16/16/15 chunks) ----
    for (int c = 0; c < 4; c++) {
        int t0 = c * 16;
        int t1 = (c == 3) ? (TT - 1) : (c * 16 + 16);
        dec_persist<<<64, 256, RSMEM2>>>(p_whTd, bh_d, p_gid, Wq, bq, p_K, p_V,
                                         p_hdec, p_hid, p_hgru, t0, t1, 4 + c);
        int m0 = c * 512;
        int mrows = (c == 3) ? (MROWS - m0) : 512;
        if (c < 3) {
            cudaEventRecord(evD[c], 0);
            cudaStreamWaitEvent(s2, evD[c], 0);
            gemm_k<1,1><<<dim3(DD / 64, 8), 256, 0, s2>>>(
                p_hid + (size_t)m0 * DD, W1, b1, xh + (size_t)m0 * DD, mrows, DD, DD);
            head_mma<<<dim3(4, VOC / 128), 256, 0, s2>>>(xh, w2h, b2, out, c * 4);
            if (c == 2) cudaEventRecord(evJoin, s2);
        } else {
            gemm_k<1,1><<<dim3(DD / 64, 8), 256>>>(
                p_hid + (size_t)m0 * DD, W1, b1, xh + (size_t)m0 * DD, mrows, DD, DD);
            head_mma<<<dim3(4, VOC / 128), 256>>>(xh, w2h, b2, out, 12);
        }
    }

    // join s2
    cudaStreamWaitEvent(0, evJoin, 0);
}

// round 15
// speedup vs baseline: 1.0791x; 1.0588x over previous
#include <cuda_runtime.h>
#include <cuda_fp16.h>
#include <cstdint>
#include <math.h>

#define BB   32
#define SS   64
#define TT   64
#define EE   256
#define HH   512
#define DD   512
#define KKQ  64
#define VOC  32000
#define G3   1536
#define MROWS (BB*(TT-1))   // 2016

#define NF_EMB   (BB*SS*EE)
#define NF_GI    (BB*SS*G3)
#define NF_WR    (BB*SS*2*HH)
#define NF_HENC  (2*BB*2*HH)
#define NF_K     (BB*SS*KKQ)
#define NF_V     (BB*SS*DD)
#define NF_DEMB  (BB*(TT-1)*EE)
#define NF_GID   (BB*(TT-1)*G3)
#define NF_HDEC  (BB*DD)
#define NF_HID   (BB*(TT-1)*DD)
#define NF_WHTE  (2*512*1536)
#define NF_WHTD  (512*1536)
#define NF_HGRU  (BB*DD)

#define NF_TOTAL (NF_EMB + 2*NF_GI + NF_WR + NF_HENC + NF_K + NF_V + NF_DEMB + NF_GID + \
                  NF_HDEC + NF_HID + NF_WHTE + NF_WHTD + NF_HGRU)

__device__ float g_scr[NF_TOTAL];
__device__ __half g_xh[MROWS * DD];
__device__ __half g_w2h[VOC * DD];
__device__ unsigned g_bars[8];   // 0..3 enc (dir,bg) groups; 4..7 dec chunks

__device__ __forceinline__ float sigm(float x) { return 1.0f / (1.0f + expf(-x)); }
__device__ __forceinline__ float gelu_f(float x) { return 0.5f * x * (1.0f + erff(x * 0.7071067811865475f)); }

__device__ __forceinline__ float ldcg1(const float* p) {
    float v; asm volatile("ld.global.cg.f32 %0, [%1];" : "=f"(v) : "l"(p)); return v;
}
__device__ __forceinline__ float4 ldcg4(const float* p) {
    float4 v;
    asm volatile("ld.global.cg.v4.f32 {%0,%1,%2,%3}, [%4];"
                 : "=f"(v.x), "=f"(v.y), "=f"(v.z), "=f"(v.w) : "l"(p));
    return v;
}

__device__ __forceinline__ void ffma2(unsigned long long& d,
                                      unsigned long long a, unsigned long long b) {
    asm("fma.rn.f32x2 %0, %1, %2, %0;" : "+l"(d) : "l"(a), "l"(b));
}
__device__ __forceinline__ unsigned long long splat2(float a) {
    unsigned long long r;
    asm("mov.b64 %0, {%1, %1};" : "=l"(r) : "f"(a));
    return r;
}
__device__ __forceinline__ float hsum2(unsigned long long v) {
    float lo = __uint_as_float((unsigned)(v & 0xffffffffull));
    float hi = __uint_as_float((unsigned)(v >> 32));
    return lo + hi;
}
__device__ __forceinline__ float lane0(unsigned long long v) {
    return __uint_as_float((unsigned)(v & 0xffffffffull));
}
__device__ __forceinline__ float lane1(unsigned long long v) {
    return __uint_as_float((unsigned)(v >> 32));
}

__device__ __forceinline__ void gsync(unsigned* bar, unsigned& epoch, unsigned nb) {
    __syncthreads();
    if (threadIdx.x == 0) {
        epoch += nb;
        __threadfence();
        atomicAdd(bar, 1u);
        while (*(volatile unsigned*)bar < epoch) __nanosleep(32);
        __threadfence();
    }
    __syncthreads();
}

// ---------------- init ----------------
__global__ void init_zero(float* __restrict__ out, float* __restrict__ henc) {
    int i = blockIdx.x * blockDim.x + threadIdx.x;
    if (i < 8) g_bars[i] = 0;
    if (i < BB * VOC) {
        int b = i / VOC;
        out[(size_t)b * TT * VOC + (i % VOC)] = 0.0f;
    }
    if (i < NF_HENC) henc[i] = 0.0f;
}

// ---------------- embedding gathers ----------------
__global__ void gather_src(const int* __restrict__ src, const float* __restrict__ tab,
                           float* __restrict__ emb) {
    int i = blockIdx.x * blockDim.x + threadIdx.x;
    if (i >= BB * SS * (EE / 4)) return;
    int row = i / (EE / 4);
    int c   = i % (EE / 4);
    ((float4*)emb)[row * (EE / 4) + c] =
        ((const float4*)tab)[(size_t)src[row] * (EE / 4) + c];
}

__global__ void gather_trg(const int* __restrict__ trg, const float* __restrict__ tab,
                           float* __restrict__ demb) {
    int i = blockIdx.x * blockDim.x + threadIdx.x;
    if (i >= BB * (TT - 1) * (EE / 4)) return;
    int m = i / (EE / 4);
    int c = i % (EE / 4);
    int t = m / BB, b = m % BB;
    int tok = trg[b * TT + t];
    ((float4*)demb)[m * (EE / 4) + c] =
        ((const float4*)tab)[(size_t)tok * (EE / 4) + c];
}

// ---------------- transpose-pack recurrent weights: [dir][j][gate][k] ----------------
__global__ void pack_whT(const float* __restrict__ Wh_f, const float* __restrict__ Wh_b,
                         const float* __restrict__ Wh_d,
                         float* __restrict__ whTe, float* __restrict__ whTd) {
    int idx = blockIdx.x * blockDim.x + threadIdx.x;
    if (idx >= 512 * 512) return;
    int k = idx >> 9, j = idx & 511;
#pragma unroll
    for (int g = 0; g < 3; g++) {
        whTe[(size_t)(j * 3 + g) * 512 + k] = Wh_f[k * G3 + g * 512 + j];
        whTe[(size_t)512 * 1536 + (j * 3 + g) * 512 + k] = Wh_b[k * G3 + g * 512 + j];
        whTd[(size_t)(j * 3 + g) * 512 + k] = Wh_d[k * G3 + g * 512 + j];
    }
}

// ---------------- generic fp32 GEMM (f32x2 inner loop) ----------------
template<int GELU, int OUT16>
__global__ void gemm_k(const float* __restrict__ A, const float* __restrict__ Bm,
                       const float* __restrict__ bias, void* __restrict__ Cv,
                       int M, int N, int K) {
    __shared__ float As[16][68];
    __shared__ float Bs[16][68];
    int tid = threadIdx.x;
    int m0 = blockIdx.y * 64, n0 = blockIdx.x * 64;
    int tx = tid & 15, ty = tid >> 4;

    unsigned long long acc2[4][2];
#pragma unroll
    for (int i = 0; i < 4; i++) { acc2[i][0] = 0ull; acc2[i][1] = 0ull; }

    int lam = tid >> 2;
    int lak = (tid & 3) * 4;
    int lbk = tid >> 4;
    int lbn = (tid & 15) * 4;

    for (int k0 = 0; k0 < K; k0 += 16) {
        float4 av = (m0 + lam < M)
            ? *(const float4*)&A[(size_t)(m0 + lam) * K + k0 + lak]
            : make_float4(0.f, 0.f, 0.f, 0.f);
        float4 bv = *(const float4*)&Bm[(size_t)(k0 + lbk) * N + n0 + lbn];
        __syncthreads();
        As[lak + 0][lam] = av.x;
        As[lak + 1][lam] = av.y;
        As[lak + 2][lam] = av.z;
        As[lak + 3][lam] = av.w;
        *(float4*)&Bs[lbk][lbn] = bv;
        __syncthreads();
#pragma unroll
        for (int kk = 0; kk < 16; kk++) {
            float4 a4 = *(const float4*)&As[kk][ty * 4];
            unsigned long long b0 = *(const unsigned long long*)&Bs[kk][tx * 4];
            unsigned long long b1 = *(const unsigned long long*)&Bs[kk][tx * 4 + 2];
            unsigned long long s0 = splat2(a4.x);
            unsigned long long s1 = splat2(a4.y);
            unsigned long long s2 = splat2(a4.z);
            unsigned long long s3 = splat2(a4.w);
            ffma2(acc2[0][0], s0, b0); ffma2(acc2[0][1], s0, b1);
            ffma2(acc2[1][0], s1, b0); ffma2(acc2[1][1], s1, b1);
            ffma2(acc2[2][0], s2, b0); ffma2(acc2[2][1], s2, b1);
            ffma2(acc2[3][0], s3, b0); ffma2(acc2[3][1], s3, b1);
        }
    }

#pragma unroll
    for (int i = 0; i < 4; i++) {
        int m = m0 + ty * 4 + i;
        if (m >= M) continue;
        float vj[4] = { lane0(acc2[i][0]), lane1(acc2[i][0]),
                        lane0(acc2[i][1]), lane1(acc2[i][1]) };
#pragma unroll
        for (int j = 0; j < 4; j++) {
            int n = n0 + tx * 4 + j;
            float v = vj[j] + bias[n];
            if (GELU) v = gelu_f(v);
            if (OUT16) ((__half*)Cv)[(size_t)m * N + n] = __float2half(v);
            else       ((float*)Cv)[(size_t)m * N + n] = v;
        }
    }
}

// ===== recurrence smem layout =====
#define WP2   1538
#define HP2   516
#define OFF_H   (16 * WP2)
#define OFF_P   (16 * WP2 + 16 * HP2)
#define RSMEM2  ((16 * WP2 + 16 * HP2 + 16 * 3 * 16 * 16) * 4)   // 180608 B

__device__ __forceinline__ void fill_wslab(float* ws, const float* wsrc, int tid) {
#pragma unroll
    for (int u = 0; u < 24; u++) {
        int idx4 = u * 256 + tid;
        int jl = idx4 / 384;
        int off = (idx4 - jl * 384) * 4;
        float4 v = *(const float4*)&wsrc[(size_t)jl * 1536 + off];
        float* d = &ws[jl * WP2 + off];
        *(float2*)d = make_float2(v.x, v.y);
        *(float2*)(d + 2) = make_float2(v.z, v.w);
    }
}

__device__ __forceinline__ void gru_core(const float* ws, const float* hsf,
                                         float* part, int tx, int ty) {
    unsigned long long acc[16][3];
#pragma unroll
    for (int b = 0; b < 16; b++)
#pragma unroll
        for (int g = 0; g < 3; g++) acc[b][g] = 0ull;

    const float* wr_p = ws + tx * WP2 + ty * 32;
    const float* wz_p = wr_p + 512;
    const float* wn_p = wr_p + 1024;
    const float* h_p  = hsf + ty * 32;

#pragma unroll
    for (int kk2 = 0; kk2 < 16; kk2++) {
        unsigned long long wr = *(const unsigned long long*)(wr_p + kk2 * 2);
        unsigned long long wz = *(const unsigned long long*)(wz_p + kk2 * 2);
        unsigned long long wn = *(const unsigned long long*)(wn_p + kk2 * 2);
#pragma unroll
        for (int b = 0; b < 16; b++) {
            unsigned long long h2 = *(const unsigned long long*)(h_p + b * HP2 + kk2 * 2);
            ffma2(acc[b][0], h2, wr);
            ffma2(acc[b][1], h2, wz);
            ffma2(acc[b][2], h2, wn);
        }
    }
#pragma unroll
    for (int b = 0; b < 16; b++)
#pragma unroll
        for (int g = 0; g < 3; g++)
            part[((b * 3 + g) * 16 + ty) * 16 + tx] = hsum2(acc[b][g]);
}

// ================= persistent encoder: 4 independent (dir,bg) barrier groups =================
__global__ void __launch_bounds__(256, 1)
enc_persist(const float* __restrict__ whTe,
            const float* __restrict__ bh_f, const float* __restrict__ bh_b,
            const int* __restrict__ src_lens,
            const float* __restrict__ gi_f, const float* __restrict__ gi_b,
            float* __restrict__ henc, float* __restrict__ wr_out) {
    extern __shared__ float smem[];
    float* ws   = smem;
    float* hsf  = smem + OFF_H;
    float* part = smem + OFF_P;

    int cta = blockIdx.x;
    int dir = cta & 1, bg = (cta >> 1) & 1, jt = cta >> 2;
    unsigned* bar = &g_bars[cta & 3];
    int tid = threadIdx.x;
    int tx = tid & 15, ty = tid >> 4;
    const float* bh = dir ? bh_b : bh_f;
    const float* gi = dir ? gi_b : gi_f;

    fill_wslab(ws, whTe + (size_t)dir * 512 * 1536 + (size_t)jt * 16 * 1536, tid);

    int j_g = jt * 16 + tx;
    int b_g = bg * 16 + ty;
    float br = bh[j_g], bz = bh[512 + j_g], bn = bh[1024 + j_g];
    int len = max(src_lens[b_g], 1);
    unsigned epoch = 0;
    __syncthreads();

    for (int step = 0; step < SS; step++) {
        int t = dir ? (SS - 1 - step) : step;
        int p = step & 1;
        const float* hin = henc + p * (BB * 1024);
        float* hout = henc + (p ^ 1) * (BB * 1024);

#pragma unroll
        for (int u = 0; u < 8; u++) {
            int idx = u * 256 + tid;
            int bl = idx >> 7, kq = idx & 127;
            float4 h4 = ldcg4(&hin[(bg * 16 + bl) * 1024 + dir * 512 + kq * 4]);
            *(float4*)&hsf[bl * HP2 + kq * 4] = h4;
        }
        __syncthreads();

        gru_core(ws, hsf, part, tx, ty);
        __syncthreads();

        {
            float sr = 0.f, sz = 0.f, sn = 0.f;
#pragma unroll
            for (int s = 0; s < 16; s++) {
                sr += part[((ty * 3 + 0) * 16 + s) * 16 + tx];
                sz += part[((ty * 3 + 1) * 16 + s) * 16 + tx];
                sn += part[((ty * 3 + 2) * 16 + s) * 16 + tx];
            }
            size_t row = (size_t)(b_g * SS + t);
            float gir = gi[row * G3 + j_g];
            float giz = gi[row * G3 + 512 + j_g];
            float gin = gi[row * G3 + 1024 + j_g];
            float hold = hsf[ty * HP2 + j_g];
            float r = sigm(gir + sr + br);
            float z = sigm(giz + sz + bz);
            float n = tanhf(gin + r * (sn + bn));
            float hnew = (1.0f - z) * n + z * hold;
            bool valid = t < len;
            hout[b_g * 1024 + dir * 512 + j_g] = valid ? hnew : hold;
            wr_out[row * 1024 + dir * 512 + j_g] = valid ? hnew : 0.0f;
        }
        gsync(bar, epoch, 32);
    }
}

// ================= persistent decoder (t-range chunk, own barrier counter) =================
__global__ void __launch_bounds__(256, 1)
dec_persist(const float* __restrict__ whTd, const float* __restrict__ bh,
            const float* __restrict__ gi,
            const float* __restrict__ Wq, const float* __restrict__ bq,
            const float* __restrict__ Kmat, const float* __restrict__ Vmat,
            float* __restrict__ hdec, float* __restrict__ hid_all,
            float* __restrict__ hgru, int t0, int t1, int bar_idx) {
    extern __shared__ float smem[];
    float* ws   = smem;
    float* hsf  = smem + OFF_H;
    float* part = smem + OFF_P;
    __shared__ float hsh[DD];
    __shared__ float qsh[KKQ];
    __shared__ float ssh[SS];
    __shared__ float red[256];

    int cta = blockIdx.x;
    int bg = cta & 1, jt = cta >> 1;
    int tid = threadIdx.x;
    int tx = tid & 15, ty = tid >> 4;
    unsigned* bar = &g_bars[bar_idx];

    fill_wslab(ws, whTd + (size_t)jt * 16 * 1536, tid);

    int j_g = jt * 16 + tx;
    int b_g = bg * 16 + ty;
    float br = bh[j_g], bz = bh[512 + j_g], bn = bh[1024 + j_g];
    unsigned epoch = 0;
    __syncthreads();

    for (int t = t0; t < t1; t++) {
#pragma unroll
        for (int u = 0; u < 4; u++) {
            int idx = u * 256 + tid;
            int bl = idx >> 6, kq = idx & 63;
            float4 h4 = ldcg4(&hdec[(bg * 16 + bl) * 512 + kq * 8]);
            float4 h4b = ldcg4(&hdec[(bg * 16 + bl) * 512 + kq * 8 + 4]);
            *(float4*)&hsf[bl * HP2 + kq * 8] = h4;
            *(float4*)&hsf[bl * HP2 + kq * 8 + 4] = h4b;
        }
        __syncthreads();

        gru_core(ws, hsf, part, tx, ty);
        __syncthreads();

        {
            float sr = 0.f, sz = 0.f, sn = 0.f;
#pragma unroll
            for (int s = 0; s < 16; s++) {
                sr += part[((ty * 3 + 0) * 16 + s) * 16 + tx];
                sz += part[((ty * 3 + 1) * 16 + s) * 16 + tx];
                sn += part[((ty * 3 + 2) * 16 + s) * 16 + tx];
            }
            size_t row = (size_t)(t * BB + b_g);
            float gir = gi[row * G3 + j_g];
            float giz = gi[row * G3 + 512 + j_g];
            float gin = gi[row * G3 + 1024 + j_g];
            float hold = hsf[ty * HP2 + j_g];
            float r = sigm(gir + sr + br);
            float z = sigm(giz + sz + bz);
            float n = tanhf(gin + r * (sn + bn));
            hgru[b_g * 512 + j_g] = (1.0f - z) * n + z * hold;
        }
        gsync(bar, epoch, gridDim.x);

        if (cta < BB) {
            int ba = cta;
            size_t rowa = (size_t)(t * BB + ba);
            for (int i = tid; i < DD; i += 256) hsh[i] = ldcg1(&hgru[ba * 512 + i]);
            __syncthreads();
            {
                int jq = tid & 63, prt = tid >> 6;
                float acc = 0.f;
                int kb = prt * 128;
                for (int k = kb; k < kb + 128; k++) acc = fmaf(hsh[k], Wq[k * KKQ + jq], acc);
                red[tid] = acc;
            }
            __syncthreads();
            if (tid < KKQ) {
                float q = red[tid] + red[tid + 64] + red[tid + 128] + red[tid + 192] + bq[tid];
                qsh[tid] = q * 0.125f;
            }
            __syncthreads();
            if (tid < SS) {
                const float* Kp = Kmat + (size_t)(ba * SS + tid) * KKQ;
                float sc = 0.f;
                for (int k = 0; k < KKQ; k++) sc = fmaf(qsh[k], Kp[k], sc);
                ssh[tid] = sc;
            }
            __syncthreads();
            if (tid == 0) {
                float m = ssh[0];
                for (int s = 1; s < SS; s++) m = fmaxf(m, ssh[s]);
                float sum = 0.f;
                for (int s = 0; s < SS; s++) { float e = expf(ssh[s] - m); ssh[s] = e; sum += e; }
                red[0] = 1.0f / sum;
            }
            __syncthreads();
            float inv = red[0];
            __syncthreads();
            if (tid < SS) ssh[tid] *= inv;
            __syncthreads();
            for (int d0 = tid; d0 < DD; d0 += 256) {
                float a = 0.f;
                for (int s = 0; s < SS; s++)
                    a = fmaf(ssh[s], Vmat[(size_t)(ba * SS + s) * DD + d0], a);
                float hid = hsh[d0] + a;
                hdec[ba * 512 + d0] = hid;
                hid_all[rowa * 512 + d0] = hid;
            }
        }
        gsync(bar, epoch, gridDim.x);
    }
}

// transpose W2 [K=512, N=32000] fp32 -> W2h [N, K] fp16
__global__ void transpose_w2(const float* __restrict__ W2, __half* __restrict__ W2h) {
    __shared__ float ts[32][33];
    int n0 = blockIdx.x * 32;
    int k0 = blockIdx.y * 32;
    int tx = threadIdx.x, ty = threadIdx.y;
#pragma unroll
    for (int j = 0; j < 4; j++)
        ts[ty + j * 8][tx] = W2[(size_t)(k0 + ty + j * 8) * VOC + n0 + tx];
    __syncthreads();
#pragma unroll
    for (int j = 0; j < 4; j++) {
        int n = n0 + ty + j * 8;
        int k = k0 + tx;
        W2h[(size_t)n * DD + k] = __float2half(ts[tx][ty + j * 8]);
    }
}

// ================= HMMA fp16 head GEMM (m-tile offset) =================
#define HPITCH 72

__device__ __forceinline__ uint32_t smem_u32(const void* p) {
    uint32_t a;
    asm("{ .reg .u64 t; cvta.to.shared.u64 t, %1; cvt.u32.u64 %0, t; }" : "=r"(a) : "l"(p));
    return a;
}
__device__ __forceinline__ void ldmatrix_x4(uint32_t* r, uint32_t addr) {
    asm volatile("ldmatrix.sync.aligned.m8n8.x4.shared.b16 {%0,%1,%2,%3}, [%4];"
                 : "=r"(r[0]), "=r"(r[1]), "=r"(r[2]), "=r"(r[3]) : "r"(addr));
}
__device__ __forceinline__ void ldmatrix_x2(uint32_t* r, uint32_t addr) {
    asm volatile("ldmatrix.sync.aligned.m8n8.x2.shared.b16 {%0,%1}, [%2];"
                 : "=r"(r[0]), "=r"(r[1]) : "r"(addr));
}
__device__ __forceinline__ void mma16816(float* c, const uint32_t* a, const uint32_t* b) {
    asm volatile(
        "mma.sync.aligned.m16n8k16.row.col.f32.f16.f16.f32 "
        "{%0,%1,%2,%3}, {%4,%5,%6,%7}, {%8,%9}, {%0,%1,%2,%3};"
        : "+f"(c[0]), "+f"(c[1]), "+f"(c[2]), "+f"(c[3])
        : "r"(a[0]), "r"(a[1]), "r"(a[2]), "r"(a[3]), "r"(b[0]), "r"(b[1]));
}

__global__ void __launch_bounds__(256, 2)
head_mma(const __half* __restrict__ Xh, const __half* __restrict__ W2h,
         const float* __restrict__ b2, float* __restrict__ out, int moff) {
    __shared__ __half As[128 * HPITCH];
    __shared__ __half Bs[128 * HPITCH];

    int tid = threadIdx.x;
    int wid = tid >> 5, lane = tid & 31;
    int m0 = (blockIdx.x + moff) * 128;
    int n0 = blockIdx.y * 128;
    int wm = (wid >> 2) * 64;
    int wn = (wid & 3) * 32;

    float c[4][4][4];
#pragma unroll
    for (int mi = 0; mi < 4; mi++)
#pragma unroll
        for (int ni = 0; ni < 4; ni++)
#pragma unroll
            for (int q = 0; q < 4; q++) c[mi][ni][q] = 0.0f;

    uint32_t as_base = smem_u32(As);
    uint32_t bs_base = smem_u32(Bs);

    for (int kc = 0; kc < 8; kc++) {
        int k0 = kc * 64;
        __syncthreads();
#pragma unroll
        for (int it = 0; it < 4; it++) {
            int idx = it * 256 + tid;
            int row = idx >> 3;
            int col = (idx & 7) * 8;
            uint4 va = (m0 + row < MROWS)
                ? *(const uint4*)(Xh + (size_t)(m0 + row) * DD + k0 + col)
                : make_uint4(0, 0, 0, 0);
            *(uint4*)(As + row * HPITCH + col) = va;
            uint4 vb = *(const uint4*)(W2h + (size_t)(n0 + row) * DD + k0 + col);
            *(uint4*)(Bs + row * HPITCH + col) = vb;
        }
        __syncthreads();

#pragma unroll
        for (int k16 = 0; k16 < 4; k16++) {
            uint32_t afrag[4][4], bfrag[4][2];
#pragma unroll
            for (int mi = 0; mi < 4; mi++) {
                int r = wm + mi * 16 + (lane & 15);
                int cl = k16 * 16 + ((lane >> 4) * 8);
                ldmatrix_x4(afrag[mi], as_base + (uint32_t)(r * HPITCH + cl) * 2);
            }
#pragma unroll
            for (int ni = 0; ni < 4; ni++) {
                int r = wn + ni * 8 + (lane & 7);
                int cl = k16 * 16 + (((lane >> 3) & 1) * 8);
                ldmatrix_x2(bfrag[ni], bs_base + (uint32_t)(r * HPITCH + cl) * 2);
            }
#pragma unroll
            for (int mi = 0; mi < 4; mi++)
#pragma unroll
                for (int ni = 0; ni < 4; ni++)
                    mma16816(c[mi][ni], afrag[mi], bfrag[ni]);
        }
    }

    int rbase = lane >> 2;
    int cbase = (lane & 3) * 2;
#pragma unroll
    for (int mi = 0; mi < 4; mi++) {
#pragma unroll
        for (int half2i = 0; half2i < 2; half2i++) {
            int m = m0 + wm + mi * 16 + rbase + half2i * 8;
            if (m >= MROWS) continue;
            int b = m & 31, t = m >> 5;
            float* orow = out + (size_t)(b * TT + t + 1) * VOC;
#pragma unroll
            for (int ni = 0; ni < 4; ni++) {
                int n = n0 + wn + ni * 8 + cbase;
                float2 v;
                v.x = c[mi][ni][half2i * 2 + 0] + b2[n];
                v.y = c[mi][ni][half2i * 2 + 1] + b2[n + 1];
                *(float2*)(orow + n) = v;
            }
        }
    }
}

// ================================ host ================================
extern "C" void kernel_launch(void* const* d_in, const int* in_sizes, int n_in,
                              void* d_out, int out_size) {
    const int*   src       = (const int*)  d_in[0];
    const int*   trg       = (const int*)  d_in[1];
    const int*   src_lens  = (const int*)  d_in[2];
    const float* enc_embed = (const float*)d_in[3];
    const float* Wi_f      = (const float*)d_in[4];
    const float* Wh_f      = (const float*)d_in[5];
    const float* bi_f      = (const float*)d_in[6];
    const float* bh_f      = (const float*)d_in[7];
    const float* Wi_b      = (const float*)d_in[8];
    const float* Wh_b      = (const float*)d_in[9];
    const float* bi_b      = (const float*)d_in[10];
    const float* bh_b      = (const float*)d_in[11];
    const float* W_e2d     = (const float*)d_in[12];
    const float* b_e2d     = (const float*)d_in[13];
    const float* dec_embed = (const float*)d_in[14];
    const float* Wi_d      = (const float*)d_in[15];
    const float* Wh_d      = (const float*)d_in[16];
    const float* bi_d      = (const float*)d_in[17];
    const float* bh_d      = (const float*)d_in[18];
    const float* Wq        = (const float*)d_in[19];
    const float* bq        = (const float*)d_in[20];
    const float* Wk        = (const float*)d_in[21];
    const float* bk        = (const float*)d_in[22];
    const float* Wv        = (const float*)d_in[23];
    const float* bv        = (const float*)d_in[24];
    const float* W1        = (const float*)d_in[25];
    const float* b1        = (const float*)d_in[26];
    const float* W2        = (const float*)d_in[27];
    const float* b2        = (const float*)d_in[28];
    float* out = (float*)d_out;

    float* scr = nullptr;
    cudaGetSymbolAddress((void**)&scr, g_scr);
    __half* xh = nullptr;
    cudaGetSymbolAddress((void**)&xh, g_xh);
    __half* w2h = nullptr;
    cudaGetSymbolAddress((void**)&w2h, g_w2h);

    float* p_emb  = scr;
    float* p_gif  = p_emb  + NF_EMB;
    float* p_gib  = p_gif  + NF_GI;
    float* p_wr   = p_gib  + NF_GI;
    float* p_henc = p_wr   + NF_WR;
    float* p_K    = p_henc + NF_HENC;
    float* p_V    = p_K    + NF_K;
    float* p_demb = p_V    + NF_V;
    float* p_gid  = p_demb + NF_DEMB;
    float* p_hdec = p_gid  + NF_GID;
    float* p_hid  = p_hdec + NF_HDEC;
    float* p_whTe = p_hid  + NF_HID;
    float* p_whTd = p_whTe + NF_WHTE;
    float* p_hgru = p_whTd + NF_WHTD;

    static cudaStream_t s2;
    static cudaEvent_t evFork, evEmb, evPack, evGib, evGid, evEnc, evV, evD[3], evJoin;
    static int once = 0;
    if (!once) {
        cudaFuncSetAttribute(enc_persist, cudaFuncAttributeMaxDynamicSharedMemorySize, RSMEM2);
        cudaFuncSetAttribute(dec_persist, cudaFuncAttributeMaxDynamicSharedMemorySize, RSMEM2);
        cudaStreamCreateWithFlags(&s2, cudaStreamNonBlocking);
        cudaEventCreateWithFlags(&evFork, cudaEventDisableTiming);
        cudaEventCreateWithFlags(&evEmb,  cudaEventDisableTiming);
        cudaEventCreateWithFlags(&evPack, cudaEventDisableTiming);
        cudaEventCreateWithFlags(&evGib,  cudaEventDisableTiming);
        cudaEventCreateWithFlags(&evGid,  cudaEventDisableTiming);
        cudaEventCreateWithFlags(&evEnc,  cudaEventDisableTiming);
        cudaEventCreateWithFlags(&evV,    cudaEventDisableTiming);
        for (int i = 0; i < 3; i++) cudaEventCreateWithFlags(&evD[i], cudaEventDisableTiming);
        cudaEventCreateWithFlags(&evJoin, cudaEventDisableTiming);
        once = 1;
    }

    // 0) init on main stream, then fork s2
    init_zero<<<(BB * VOC + 255) / 256, 256>>>(out, p_henc);
    cudaEventRecord(evFork, 0);
    cudaStreamWaitEvent(s2, evFork, 0);

    // ---- main: encoder embeddings + gi_f ----
    gather_src<<<(BB * SS * (EE / 4) + 255) / 256, 256>>>(src, enc_embed, p_emb);
    cudaEventRecord(evEmb, 0);
    gemm_k<0,0><<<dim3(G3 / 64, (BB * SS) / 64), 256>>>(p_emb, Wi_f, bi_f, p_gif, BB * SS, G3, EE);

    // ---- s2: pack weights early, then gi_b (concurrent with gi_f), then deferred prep ----
    pack_whT<<<(512 * 512 + 255) / 256, 256, 0, s2>>>(Wh_f, Wh_b, Wh_d, p_whTe, p_whTd);
    cudaEventRecord(evPack, s2);
    cudaStreamWaitEvent(s2, evEmb, 0);
    gemm_k<0,0><<<dim3(G3 / 64, (BB * SS) / 64), 256, 0, s2>>>(p_emb, Wi_b, bi_b, p_gib, BB * SS, G3, EE);
    cudaEventRecord(evGib, s2);
    transpose_w2<<<dim3(VOC / 32, DD / 32), dim3(32, 8), 0, s2>>>(W2, w2h);
    gather_trg<<<(BB * (TT - 1) * (EE / 4) + 255) / 256, 256, 0, s2>>>(trg, dec_embed, p_demb);
    gemm_k<0,0><<<dim3(G3 / 64, (BB * (TT - 1) + 63) / 64), 256, 0, s2>>>(
        p_demb, Wi_d, bi_d, p_gid, BB * (TT - 1), G3, EE);
    cudaEventRecord(evGid, s2);

    // ---- main: encoder recurrence ----
    cudaStreamWaitEvent(0, evPack, 0);
    cudaStreamWaitEvent(0, evGib, 0);
    enc_persist<<<128, 256, RSMEM2>>>(p_whTe, bh_f, bh_b, src_lens, p_gif, p_gib, p_henc, p_wr);
    cudaEventRecord(evEnc, 0);
    float* p_sent = p_henc;

    // ---- main: K + e2d; s2: V (concurrent) ----
    gemm_k<0,0><<<dim3(KKQ / 64, (BB * SS) / 64), 256>>>(p_wr, Wk, bk, p_K, BB * SS, KKQ, 2 * HH);
    gemm_k<1,0><<<dim3(DD / 64, 1), 256>>>(p_sent, W_e2d, b_e2d, p_hdec, BB, DD, 2 * HH);
    cudaStreamWaitEvent(s2, evEnc, 0);
    gemm_k<0,0><<<dim3(DD / 64, (BB * SS) / 64), 256, 0, s2>>>(p_wr, Wv, bv, p_V, BB * SS, DD, 2 * HH);
    cudaEventRecord(evV, s2);

    cudaStreamWaitEvent(0, evGid, 0);
    cudaStreamWaitEvent(0, evV, 0);

    // ---- 4-way decoder/head pipeline (16/16/16/15 chunks) ----
    for (int c = 0; c < 4; c++) {
        int t0 = c * 16;
        int t1 = (c == 3) ? (TT - 1) : (c * 16 + 16);
        dec_persist<<<64, 256, RSMEM2>>>(p_whTd, bh_d, p_gid, Wq, bq, p_K, p_V,
                                         p_hdec, p_hid, p_hgru, t0, t1, 4 + c);
        int m0 = c * 512;
        int mrows = (c == 3) ? (MROWS - m0) : 512;
        if (c < 3) {
            cudaEventRecord(evD[c], 0);
            cudaStreamWaitEvent(s2, evD[c], 0);
            gemm_k<1,1><<<dim3(DD / 64, 8), 256, 0, s2>>>(
                p_hid + (size_t)m0 * DD, W1, b1, xh + (size_t)m0 * DD, mrows, DD, DD);
            head_mma<<<dim3(4, VOC / 128), 256, 0, s2>>>(xh, w2h, b2, out, c * 4);
            if (c == 2) cudaEventRecord(evJoin, s2);
        } else {
            gemm_k<1,1><<<dim3(DD / 64, 8), 256>>>(
                p_hid + (size_t)m0 * DD, W1, b1, xh + (size_t)m0 * DD, mrows, DD, DD);
            head_mma<<<dim3(4, VOC / 128), 256>>>(xh, w2h, b2, out, 12);
        }
    }

    // join s2
    cudaStreamWaitEvent(0, evJoin, 0);
}

// round 16
// speedup vs baseline: 1.1589x; 1.0740x over previous
#include <cuda_runtime.h>
#include <cuda_fp16.h>
#include <cstdint>
#include <math.h>

#define BB   32
#define SS   64
#define TT   64
#define EE   256
#define HH   512
#define DD   512
#define KKQ  64
#define VOC  32000
#define G3   1536
#define MROWS (BB*(TT-1))   // 2016

#define NF_EMB   (BB*SS*EE)
#define NF_GI    (BB*SS*G3)
#define NF_WR    (BB*SS*2*HH)
#define NF_HENC  (2*BB*2*HH)
#define NF_K     (BB*SS*KKQ)
#define NF_V     (BB*SS*DD)
#define NF_DEMB  (BB*(TT-1)*EE)
#define NF_GID   (BB*(TT-1)*G3)
#define NF_HDEC  (BB*DD)
#define NF_HID   (BB*(TT-1)*DD)
#define NF_WHTE  (2*512*1536)
#define NF_WHTD  (512*1536)
#define NF_HGRU  (BB*DD)

#define NF_TOTAL (NF_EMB + 2*NF_GI + NF_WR + NF_HENC + NF_K + NF_V + NF_DEMB + NF_GID + \
                  NF_HDEC + NF_HID + NF_WHTE + NF_WHTD + NF_HGRU)

__device__ float g_scr[NF_TOTAL];
__device__ __half g_xh[MROWS * DD];
__device__ __half g_w2h[VOC * DD];
__device__ unsigned g_bars[8];   // 0..3 enc (dir,bg) groups; 4..7 dec chunks

__device__ __forceinline__ float sigm(float x) { return 1.0f / (1.0f + expf(-x)); }
__device__ __forceinline__ float gelu_f(float x) { return 0.5f * x * (1.0f + erff(x * 0.7071067811865475f)); }

__device__ __forceinline__ float ldcg1(const float* p) {
    float v; asm volatile("ld.global.cg.f32 %0, [%1];" : "=f"(v) : "l"(p)); return v;
}
__device__ __forceinline__ float4 ldcg4(const float* p) {
    float4 v;
    asm volatile("ld.global.cg.v4.f32 {%0,%1,%2,%3}, [%4];"
                 : "=f"(v.x), "=f"(v.y), "=f"(v.z), "=f"(v.w) : "l"(p));
    return v;
}

__device__ __forceinline__ void ffma2(unsigned long long& d,
                                      unsigned long long a, unsigned long long b) {
    asm("fma.rn.f32x2 %0, %1, %2, %0;" : "+l"(d) : "l"(a), "l"(b));
}
__device__ __forceinline__ unsigned long long splat2(float a) {
    unsigned long long r;
    asm("mov.b64 %0, {%1, %1};" : "=l"(r) : "f"(a));
    return r;
}
__device__ __forceinline__ float hsum2(unsigned long long v) {
    float lo = __uint_as_float((unsigned)(v & 0xffffffffull));
    float hi = __uint_as_float((unsigned)(v >> 32));
    return lo + hi;
}
__device__ __forceinline__ float lane0(unsigned long long v) {
    return __uint_as_float((unsigned)(v & 0xffffffffull));
}
__device__ __forceinline__ float lane1(unsigned long long v) {
    return __uint_as_float((unsigned)(v >> 32));
}

// software barrier: release/acquire semantics (grid.sync pattern, no membar.gpu)
__device__ __forceinline__ void gsync(unsigned* bar, unsigned& epoch, unsigned nb) {
    __syncthreads();
    if (threadIdx.x == 0) {
        epoch += nb;
        asm volatile("red.release.gpu.global.add.u32 [%0], %1;"
                     :: "l"(bar), "r"(1u) : "memory");
        unsigned v;
        do {
            asm volatile("ld.acquire.gpu.global.u32 %0, [%1];"
                         : "=r"(v) : "l"(bar) : "memory");
            if (v >= epoch) break;
            __nanosleep(32);
        } while (true);
    }
    __syncthreads();
}

// ---------------- init ----------------
__global__ void init_zero(float* __restrict__ out, float* __restrict__ henc) {
    int i = blockIdx.x * blockDim.x + threadIdx.x;
    if (i < 8) g_bars[i] = 0;
    if (i < BB * VOC) {
        int b = i / VOC;
        out[(size_t)b * TT * VOC + (i % VOC)] = 0.0f;
    }
    if (i < NF_HENC) henc[i] = 0.0f;
}

// ---------------- embedding gathers ----------------
__global__ void gather_src(const int* __restrict__ src, const float* __restrict__ tab,
                           float* __restrict__ emb) {
    int i = blockIdx.x * blockDim.x + threadIdx.x;
    if (i >= BB * SS * (EE / 4)) return;
    int row = i / (EE / 4);
    int c   = i % (EE / 4);
    ((float4*)emb)[row * (EE / 4) + c] =
        ((const float4*)tab)[(size_t)src[row] * (EE / 4) + c];
}

__global__ void gather_trg(const int* __restrict__ trg, const float* __restrict__ tab,
                           float* __restrict__ demb) {
    int i = blockIdx.x * blockDim.x + threadIdx.x;
    if (i >= BB * (TT - 1) * (EE / 4)) return;
    int m = i / (EE / 4);
    int c = i % (EE / 4);
    int t = m / BB, b = m % BB;
    int tok = trg[b * TT + t];
    ((float4*)demb)[m * (EE / 4) + c] =
        ((const float4*)tab)[(size_t)tok * (EE / 4) + c];
}

// ---------------- transpose-pack recurrent weights: [dir][j][gate][k] ----------------
__global__ void pack_whT(const float* __restrict__ Wh_f, const float* __restrict__ Wh_b,
                         const float* __restrict__ Wh_d,
                         float* __restrict__ whTe, float* __restrict__ whTd) {
    int idx = blockIdx.x * blockDim.x + threadIdx.x;
    if (idx >= 512 * 512) return;
    int k = idx >> 9, j = idx & 511;
#pragma unroll
    for (int g = 0; g < 3; g++) {
        whTe[(size_t)(j * 3 + g) * 512 + k] = Wh_f[k * G3 + g * 512 + j];
        whTe[(size_t)512 * 1536 + (j * 3 + g) * 512 + k] = Wh_b[k * G3 + g * 512 + j];
        whTd[(size_t)(j * 3 + g) * 512 + k] = Wh_d[k * G3 + g * 512 + j];
    }
}

// ---------------- generic fp32 GEMM (f32x2 inner loop) ----------------
template<int GELU, int OUT16>
__global__ void gemm_k(const float* __restrict__ A, const float* __restrict__ Bm,
                       const float* __restrict__ bias, void* __restrict__ Cv,
                       int M, int N, int K) {
    __shared__ float As[16][68];
    __shared__ float Bs[16][68];
    int tid = threadIdx.x;
    int m0 = blockIdx.y * 64, n0 = blockIdx.x * 64;
    int tx = tid & 15, ty = tid >> 4;

    unsigned long long acc2[4][2];
#pragma unroll
    for (int i = 0; i < 4; i++) { acc2[i][0] = 0ull; acc2[i][1] = 0ull; }

    int lam = tid >> 2;
    int lak = (tid & 3) * 4;
    int lbk = tid >> 4;
    int lbn = (tid & 15) * 4;

    for (int k0 = 0; k0 < K; k0 += 16) {
        float4 av = (m0 + lam < M)
            ? *(const float4*)&A[(size_t)(m0 + lam) * K + k0 + lak]
            : make_float4(0.f, 0.f, 0.f, 0.f);
        float4 bv = *(const float4*)&Bm[(size_t)(k0 + lbk) * N + n0 + lbn];
        __syncthreads();
        As[lak + 0][lam] = av.x;
        As[lak + 1][lam] = av.y;
        As[lak + 2][lam] = av.z;
        As[lak + 3][lam] = av.w;
        *(float4*)&Bs[lbk][lbn] = bv;
        __syncthreads();
#pragma unroll
        for (int kk = 0; kk < 16; kk++) {
            float4 a4 = *(const float4*)&As[kk][ty * 4];
            unsigned long long b0 = *(const unsigned long long*)&Bs[kk][tx * 4];
            unsigned long long b1 = *(const unsigned long long*)&Bs[kk][tx * 4 + 2];
            unsigned long long s0 = splat2(a4.x);
            unsigned long long s1 = splat2(a4.y);
            unsigned long long s2 = splat2(a4.z);
            unsigned long long s3 = splat2(a4.w);
            ffma2(acc2[0][0], s0, b0); ffma2(acc2[0][1], s0, b1);
            ffma2(acc2[1][0], s1, b0); ffma2(acc2[1][1], s1, b1);
            ffma2(acc2[2][0], s2, b0); ffma2(acc2[2][1], s2, b1);
            ffma2(acc2[3][0], s3, b0); ffma2(acc2[3][1], s3, b1);
        }
    }

#pragma unroll
    for (int i = 0; i < 4; i++) {
        int m = m0 + ty * 4 + i;
        if (m >= M) continue;
        float vj[4] = { lane0(acc2[i][0]), lane1(acc2[i][0]),
                        lane0(acc2[i][1]), lane1(acc2[i][1]) };
#pragma unroll
        for (int j = 0; j < 4; j++) {
            int n = n0 + tx * 4 + j;
            float v = vj[j] + bias[n];
            if (GELU) v = gelu_f(v);
            if (OUT16) ((__half*)Cv)[(size_t)m * N + n] = __float2half(v);
            else       ((float*)Cv)[(size_t)m * N + n] = v;
        }
    }
}

// ===== recurrence smem layout =====
#define WP2   1538
#define HP2   516
#define OFF_H   (16 * WP2)
#define OFF_P   (16 * WP2 + 16 * HP2)
#define RSMEM2  ((16 * WP2 + 16 * HP2 + 16 * 3 * 16 * 16) * 4)   // 180608 B

__device__ __forceinline__ void fill_wslab(float* ws, const float* wsrc, int tid) {
#pragma unroll
    for (int u = 0; u < 24; u++) {
        int idx4 = u * 256 + tid;
        int jl = idx4 / 384;
        int off = (idx4 - jl * 384) * 4;
        float4 v = *(const float4*)&wsrc[(size_t)jl * 1536 + off];
        float* d = &ws[jl * WP2 + off];
        *(float2*)d = make_float2(v.x, v.y);
        *(float2*)(d + 2) = make_float2(v.z, v.w);
    }
}

__device__ __forceinline__ void gru_core(const float* ws, const float* hsf,
                                         float* part, int tx, int ty) {
    unsigned long long acc[16][3];
#pragma unroll
    for (int b = 0; b < 16; b++)
#pragma unroll
        for (int g = 0; g < 3; g++) acc[b][g] = 0ull;

    const float* wr_p = ws + tx * WP2 + ty * 32;
    const float* wz_p = wr_p + 512;
    const float* wn_p = wr_p + 1024;
    const float* h_p  = hsf + ty * 32;

#pragma unroll
    for (int kk2 = 0; kk2 < 16; kk2++) {
        unsigned long long wr = *(const unsigned long long*)(wr_p + kk2 * 2);
        unsigned long long wz = *(const unsigned long long*)(wz_p + kk2 * 2);
        unsigned long long wn = *(const unsigned long long*)(wn_p + kk2 * 2);
#pragma unroll
        for (int b = 0; b < 16; b++) {
            unsigned long long h2 = *(const unsigned long long*)(h_p + b * HP2 + kk2 * 2);
            ffma2(acc[b][0], h2, wr);
            ffma2(acc[b][1], h2, wz);
            ffma2(acc[b][2], h2, wn);
        }
    }
#pragma unroll
    for (int b = 0; b < 16; b++)
#pragma unroll
        for (int g = 0; g < 3; g++)
            part[((b * 3 + g) * 16 + ty) * 16 + tx] = hsum2(acc[b][g]);
}

// ================= persistent encoder: 4 independent (dir,bg) barrier groups =================
__global__ void __launch_bounds__(256, 1)
enc_persist(const float* __restrict__ whTe,
            const float* __restrict__ bh_f, const float* __restrict__ bh_b,
            const int* __restrict__ src_lens,
            const float* __restrict__ gi_f, const float* __restrict__ gi_b,
            float* __restrict__ henc, float* __restrict__ wr_out) {
    extern __shared__ float smem[];
    float* ws   = smem;
    float* hsf  = smem + OFF_H;
    float* part = smem + OFF_P;

    int cta = blockIdx.x;
    int dir = cta & 1, bg = (cta >> 1) & 1, jt = cta >> 2;
    unsigned* bar = &g_bars[cta & 3];
    int tid = threadIdx.x;
    int tx = tid & 15, ty = tid >> 4;
    const float* bh = dir ? bh_b : bh_f;
    const float* gi = dir ? gi_b : gi_f;

    fill_wslab(ws, whTe + (size_t)dir * 512 * 1536 + (size_t)jt * 16 * 1536, tid);

    int j_g = jt * 16 + tx;
    int b_g = bg * 16 + ty;
    float br = bh[j_g], bz = bh[512 + j_g], bn = bh[1024 + j_g];
    int len = max(src_lens[b_g], 1);
    unsigned epoch = 0;
    __syncthreads();

    for (int step = 0; step < SS; step++) {
        int t = dir ? (SS - 1 - step) : step;
        int p = step & 1;
        const float* hin = henc + p * (BB * 1024);
        float* hout = henc + (p ^ 1) * (BB * 1024);

#pragma unroll
        for (int u = 0; u < 8; u++) {
            int idx = u * 256 + tid;
            int bl = idx >> 7, kq = idx & 127;
            float4 h4 = ldcg4(&hin[(bg * 16 + bl) * 1024 + dir * 512 + kq * 4]);
            *(float4*)&hsf[bl * HP2 + kq * 4] = h4;
        }
        __syncthreads();

        gru_core(ws, hsf, part, tx, ty);
        __syncthreads();

        {
            float sr = 0.f, sz = 0.f, sn = 0.f;
#pragma unroll
            for (int s = 0; s < 16; s++) {
                sr += part[((ty * 3 + 0) * 16 + s) * 16 + tx];
                sz += part[((ty * 3 + 1) * 16 + s) * 16 + tx];
                sn += part[((ty * 3 + 2) * 16 + s) * 16 + tx];
            }
            size_t row = (size_t)(b_g * SS + t);
            float gir = gi[row * G3 + j_g];
            float giz = gi[row * G3 + 512 + j_g];
            float gin = gi[row * G3 + 1024 + j_g];
            float hold = hsf[ty * HP2 + j_g];
            float r = sigm(gir + sr + br);
            float z = sigm(giz + sz + bz);
            float n = tanhf(gin + r * (sn + bn));
            float hnew = (1.0f - z) * n + z * hold;
            bool valid = t < len;
            hout[b_g * 1024 + dir * 512 + j_g] = valid ? hnew : hold;
            wr_out[row * 1024 + dir * 512 + j_g] = valid ? hnew : 0.0f;
        }
        gsync(bar, epoch, 32);
    }
}

// ================= persistent decoder (t-range chunk, own barrier counter) =================
// attention split over all 64 CTAs: 2 per batch (ba = cta>>1, d-half = cta&1)
__global__ void __launch_bounds__(256, 1)
dec_persist(const float* __restrict__ whTd, const float* __restrict__ bh,
            const float* __restrict__ gi,
            const float* __restrict__ Wq, const float* __restrict__ bq,
            const float* __restrict__ Kmat, const float* __restrict__ Vmat,
            float* __restrict__ hdec, float* __restrict__ hid_all,
            float* __restrict__ hgru, int t0, int t1, int bar_idx) {
    extern __shared__ float smem[];
    float* ws   = smem;
    float* hsf  = smem + OFF_H;
    float* part = smem + OFF_P;
    __shared__ float hsh[DD];
    __shared__ float qsh[KKQ];
    __shared__ float ssh[SS];
    __shared__ float red[256];

    int cta = blockIdx.x;
    int bg = cta & 1, jt = cta >> 1;
    int tid = threadIdx.x;
    int tx = tid & 15, ty = tid >> 4;
    unsigned* bar = &g_bars[bar_idx];
    int ba = cta >> 1;            // attention batch (0..31)
    int dh = (cta & 1) * 256;     // attention d-half offset

    fill_wslab(ws, whTd + (size_t)jt * 16 * 1536, tid);

    int j_g = jt * 16 + tx;
    int b_g = bg * 16 + ty;
    float br = bh[j_g], bz = bh[512 + j_g], bn = bh[1024 + j_g];
    unsigned epoch = 0;
    __syncthreads();

    for (int t = t0; t < t1; t++) {
#pragma unroll
        for (int u = 0; u < 4; u++) {
            int idx = u * 256 + tid;
            int bl = idx >> 6, kq = idx & 63;
            float4 h4 = ldcg4(&hdec[(bg * 16 + bl) * 512 + kq * 8]);
            float4 h4b = ldcg4(&hdec[(bg * 16 + bl) * 512 + kq * 8 + 4]);
            *(float4*)&hsf[bl * HP2 + kq * 8] = h4;
            *(float4*)&hsf[bl * HP2 + kq * 8 + 4] = h4b;
        }
        __syncthreads();

        gru_core(ws, hsf, part, tx, ty);
        __syncthreads();

        {
            float sr = 0.f, sz = 0.f, sn = 0.f;
#pragma unroll
            for (int s = 0; s < 16; s++) {
                sr += part[((ty * 3 + 0) * 16 + s) * 16 + tx];
                sz += part[((ty * 3 + 1) * 16 + s) * 16 + tx];
                sn += part[((ty * 3 + 2) * 16 + s) * 16 + tx];
            }
            size_t row = (size_t)(t * BB + b_g);
            float gir = gi[row * G3 + j_g];
            float giz = gi[row * G3 + 512 + j_g];
            float gin = gi[row * G3 + 1024 + j_g];
            float hold = hsf[ty * HP2 + j_g];
            float r = sigm(gir + sr + br);
            float z = sigm(giz + sz + bz);
            float n = tanhf(gin + r * (sn + bn));
            hgru[b_g * 512 + j_g] = (1.0f - z) * n + z * hold;
        }
        gsync(bar, epoch, gridDim.x);

        // attention: 2 CTAs per batch; softmax recomputed redundantly (deterministic)
        {
            size_t rowa = (size_t)(t * BB + ba);
            for (int i = tid; i < DD; i += 256) hsh[i] = ldcg1(&hgru[ba * 512 + i]);
            __syncthreads();
            {
                int jq = tid & 63, prt = tid >> 6;
                float acc = 0.f;
                int kb = prt * 128;
                for (int k = kb; k < kb + 128; k++) acc = fmaf(hsh[k], Wq[k * KKQ + jq], acc);
                red[tid] = acc;
            }
            __syncthreads();
            if (tid < KKQ) {
                float q = red[tid] + red[tid + 64] + red[tid + 128] + red[tid + 192] + bq[tid];
                qsh[tid] = q * 0.125f;
            }
            __syncthreads();
            if (tid < SS) {
                const float* Kp = Kmat + (size_t)(ba * SS + tid) * KKQ;
                float sc = 0.f;
                for (int k = 0; k < KKQ; k++) sc = fmaf(qsh[k], Kp[k], sc);
                ssh[tid] = sc;
            }
            __syncthreads();
            if (tid == 0) {
                float m = ssh[0];
                for (int s = 1; s < SS; s++) m = fmaxf(m, ssh[s]);
                float sum = 0.f;
                for (int s = 0; s < SS; s++) { float e = expf(ssh[s] - m); ssh[s] = e; sum += e; }
                red[0] = 1.0f / sum;
            }
            __syncthreads();
            float inv = red[0];
            __syncthreads();
            if (tid < SS) ssh[tid] *= inv;
            __syncthreads();
            {
                int d0 = dh + tid;   // this CTA's 256-wide d-half, 1 elem/thread
                float a = 0.f;
                for (int s = 0; s < SS; s++)
                    a = fmaf(ssh[s], Vmat[(size_t)(ba * SS + s) * DD + d0], a);
                float hid = hsh[d0] + a;
                hdec[ba * 512 + d0] = hid;
                hid_all[rowa * 512 + d0] = hid;
            }
        }
        gsync(bar, epoch, gridDim.x);
    }
}

// transpose W2 [K=512, N=32000] fp32 -> W2h [N, K] fp16
__global__ void transpose_w2(const float* __restrict__ W2, __half* __restrict__ W2h) {
    __shared__ float ts[32][33];
    int n0 = blockIdx.x * 32;
    int k0 = blockIdx.y * 32;
    int tx = threadIdx.x, ty = threadIdx.y;
#pragma unroll
    for (int j = 0; j < 4; j++)
        ts[ty + j * 8][tx] = W2[(size_t)(k0 + ty + j * 8) * VOC + n0 + tx];
    __syncthreads();
#pragma unroll
    for (int j = 0; j < 4; j++) {
        int n = n0 + ty + j * 8;
        int k = k0 + tx;
        W2h[(size_t)n * DD + k] = __float2half(ts[tx][ty + j * 8]);
    }
}

// ================= HMMA fp16 head GEMM (m-tile offset) =================
#define HPITCH 72

__device__ __forceinline__ uint32_t smem_u32(const void* p) {
    uint32_t a;
    asm("{ .reg .u64 t; cvta.to.shared.u64 t, %1; cvt.u32.u64 %0, t; }" : "=r"(a) : "l"(p));
    return a;
}
__device__ __forceinline__ void ldmatrix_x4(uint32_t* r, uint32_t addr) {
    asm volatile("ldmatrix.sync.aligned.m8n8.x4.shared.b16 {%0,%1,%2,%3}, [%4];"
                 : "=r"(r[0]), "=r"(r[1]), "=r"(r[2]), "=r"(r[3]) : "r"(addr));
}
__device__ __forceinline__ void ldmatrix_x2(uint32_t* r, uint32_t addr) {
    asm volatile("ldmatrix.sync.aligned.m8n8.x2.shared.b16 {%0,%1}, [%2];"
                 : "=r"(r[0]), "=r"(r[1]) : "r"(addr));
}
__device__ __forceinline__ void mma16816(float* c, const uint32_t* a, const uint32_t* b) {
    asm volatile(
        "mma.sync.aligned.m16n8k16.row.col.f32.f16.f16.f32 "
        "{%0,%1,%2,%3}, {%4,%5,%6,%7}, {%8,%9}, {%0,%1,%2,%3};"
        : "+f"(c[0]), "+f"(c[1]), "+f"(c[2]), "+f"(c[3])
        : "r"(a[0]), "r"(a[1]), "r"(a[2]), "r"(a[3]), "r"(b[0]), "r"(b[1]));
}

__global__ void __launch_bounds__(256, 2)
head_mma(const __half* __restrict__ Xh, const __half* __restrict__ W2h,
         const float* __restrict__ b2, float* __restrict__ out, int moff) {
    __shared__ __half As[128 * HPITCH];
    __shared__ __half Bs[128 * HPITCH];

    int tid = threadIdx.x;
    int wid = tid >> 5, lane = tid & 31;
    int m0 = (blockIdx.x + moff) * 128;
    int n0 = blockIdx.y * 128;
    int wm = (wid >> 2) * 64;
    int wn = (wid & 3) * 32;

    float c[4][4][4];
#pragma unroll
    for (int mi = 0; mi < 4; mi++)
#pragma unroll
        for (int ni = 0; ni < 4; ni++)
#pragma unroll
            for (int q = 0; q < 4; q++) c[mi][ni][q] = 0.0f;

    uint32_t as_base = smem_u32(As);
    uint32_t bs_base = smem_u32(Bs);

    for (int kc = 0; kc < 8; kc++) {
        int k0 = kc * 64;
        __syncthreads();
#pragma unroll
        for (int it = 0; it < 4; it++) {
            int idx = it * 256 + tid;
            int row = idx >> 3;
            int col = (idx & 7) * 8;
            uint4 va = (m0 + row < MROWS)
                ? *(const uint4*)(Xh + (size_t)(m0 + row) * DD + k0 + col)
                : make_uint4(0, 0, 0, 0);
            *(uint4*)(As + row * HPITCH + col) = va;
            uint4 vb = *(const uint4*)(W2h + (size_t)(n0 + row) * DD + k0 + col);
            *(uint4*)(Bs + row * HPITCH + col) = vb;
        }
        __syncthreads();

#pragma unroll
        for (int k16 = 0; k16 < 4; k16++) {
            uint32_t afrag[4][4], bfrag[4][2];
#pragma unroll
            for (int mi = 0; mi < 4; mi++) {
                int r = wm + mi * 16 + (lane & 15);
                int cl = k16 * 16 + ((lane >> 4) * 8);
                ldmatrix_x4(afrag[mi], as_base + (uint32_t)(r * HPITCH + cl) * 2);
            }
#pragma unroll
            for (int ni = 0; ni < 4; ni++) {
                int r = wn + ni * 8 + (lane & 7);
                int cl = k16 * 16 + (((lane >> 3) & 1) * 8);
                ldmatrix_x2(bfrag[ni], bs_base + (uint32_t)(r * HPITCH + cl) * 2);
            }
#pragma unroll
            for (int mi = 0; mi < 4; mi++)
#pragma unroll
                for (int ni = 0; ni < 4; ni++)
                    mma16816(c[mi][ni], afrag[mi], bfrag[ni]);
        }
    }

    int rbase = lane >> 2;
    int cbase = (lane & 3) * 2;
#pragma unroll
    for (int mi = 0; mi < 4; mi++) {
#pragma unroll
        for (int half2i = 0; half2i < 2; half2i++) {
            int m = m0 + wm + mi * 16 + rbase + half2i * 8;
            if (m >= MROWS) continue;
            int b = m & 31, t = m >> 5;
            float* orow = out + (size_t)(b * TT + t + 1) * VOC;
#pragma unroll
            for (int ni = 0; ni < 4; ni++) {
                int n = n0 + wn + ni * 8 + cbase;
                float2 v;
                v.x = c[mi][ni][half2i * 2 + 0] + b2[n];
                v.y = c[mi][ni][half2i * 2 + 1] + b2[n + 1];
                *(float2*)(orow + n) = v;
            }
        }
    }
}

// ================================ host ================================
extern "C" void kernel_launch(void* const* d_in, const int* in_sizes, int n_in,
                              void* d_out, int out_size) {
    const int*   src       = (const int*)  d_in[0];
    const int*   trg       = (const int*)  d_in[1];
    const int*   src_lens  = (const int*)  d_in[2];
    const float* enc_embed = (const float*)d_in[3];
    const float* Wi_f      = (const float*)d_in[4];
    const float* Wh_f      = (const float*)d_in[5];
    const float* bi_f      = (const float*)d_in[6];
    const float* bh_f      = (const float*)d_in[7];
    const float* Wi_b      = (const float*)d_in[8];
    const float* Wh_b      = (const float*)d_in[9];
    const float* bi_b      = (const float*)d_in[10];
    const float* bh_b      = (const float*)d_in[11];
    const float* W_e2d     = (const float*)d_in[12];
    const float* b_e2d     = (const float*)d_in[13];
    const float* dec_embed = (const float*)d_in[14];
    const float* Wi_d      = (const float*)d_in[15];
    const float* Wh_d      = (const float*)d_in[16];
    const float* bi_d      = (const float*)d_in[17];
    const float* bh_d      = (const float*)d_in[18];
    const float* Wq        = (const float*)d_in[19];
    const float* bq        = (const float*)d_in[20];
    const float* Wk        = (const float*)d_in[21];
    const float* bk        = (const float*)d_in[22];
    const float* Wv        = (const float*)d_in[23];
    const float* bv        = (const float*)d_in[24];
    const float* W1        = (const float*)d_in[25];
    const float* b1        = (const float*)d_in[26];
    const float* W2        = (const float*)d_in[27];
    const float* b2        = (const float*)d_in[28];
    float* out = (float*)d_out;

    float* scr = nullptr;
    cudaGetSymbolAddress((void**)&scr, g_scr);
    __half* xh = nullptr;
    cudaGetSymbolAddress((void**)&xh, g_xh);
    __half* w2h = nullptr;
    cudaGetSymbolAddress((void**)&w2h, g_w2h);

    float* p_emb  = scr;
    float* p_gif  = p_emb  + NF_EMB;
    float* p_gib  = p_gif  + NF_GI;
    float* p_wr   = p_gib  + NF_GI;
    float* p_henc = p_wr   + NF_WR;
    float* p_K    = p_henc + NF_HENC;
    float* p_V    = p_K    + NF_K;
    float* p_demb = p_V    + NF_V;
    float* p_gid  = p_demb + NF_DEMB;
    float* p_hdec = p_gid  + NF_GID;
    float* p_hid  = p_hdec + NF_HDEC;
    float* p_whTe = p_hid  + NF_HID;
    float* p_whTd = p_whTe + NF_WHTE;
    float* p_hgru = p_whTd + NF_WHTD;

    static cudaStream_t s2;
    static cudaEvent_t evFork, evEmb, evPack, evGib, evGid, evEnc, evV, evD[3], evJoin;
    static int once = 0;
    if (!once) {
        cudaFuncSetAttribute(enc_persist, cudaFuncAttributeMaxDynamicSharedMemorySize, RSMEM2);
        cudaFuncSetAttribute(dec_persist, cudaFuncAttributeMaxDynamicSharedMemorySize, RSMEM2);
        cudaStreamCreateWithFlags(&s2, cudaStreamNonBlocking);
        cudaEventCreateWithFlags(&evFork, cudaEventDisableTiming);
        cudaEventCreateWithFlags(&evEmb,  cudaEventDisableTiming);
        cudaEventCreateWithFlags(&evPack, cudaEventDisableTiming);
        cudaEventCreateWithFlags(&evGib,  cudaEventDisableTiming);
        cudaEventCreateWithFlags(&evGid,  cudaEventDisableTiming);
        cudaEventCreateWithFlags(&evEnc,  cudaEventDisableTiming);
        cudaEventCreateWithFlags(&evV,    cudaEventDisableTiming);
        for (int i = 0; i < 3; i++) cudaEventCreateWithFlags(&evD[i], cudaEventDisableTiming);
        cudaEventCreateWithFlags(&evJoin, cudaEventDisableTiming);
        once = 1;
    }

    // 0) init on main stream, then fork s2
    init_zero<<<(BB * VOC + 255) / 256, 256>>>(out, p_henc);
    cudaEventRecord(evFork, 0);
    cudaStreamWaitEvent(s2, evFork, 0);

    // ---- main: encoder embeddings + gi_f ----
    gather_src<<<(BB * SS * (EE / 4) + 255) / 256, 256>>>(src, enc_embed, p_emb);
    cudaEventRecord(evEmb, 0);
    gemm_k<0,0><<<dim3(G3 / 64, (BB * SS) / 64), 256>>>(p_emb, Wi_f, bi_f, p_gif, BB * SS, G3, EE);

    // ---- s2: pack weights early, then gi_b (concurrent with gi_f), then deferred prep ----
    pack_whT<<<(512 * 512 + 255) / 256, 256, 0, s2>>>(Wh_f, Wh_b, Wh_d, p_whTe, p_whTd);
    cudaEventRecord(evPack, s2);
    cudaStreamWaitEvent(s2, evEmb, 0);
    gemm_k<0,0><<<dim3(G3 / 64, (BB * SS) / 64), 256, 0, s2>>>(p_emb, Wi_b, bi_b, p_gib, BB * SS, G3, EE);
    cudaEventRecord(evGib, s2);
    transpose_w2<<<dim3(VOC / 32, DD / 32), dim3(32, 8), 0, s2>>>(W2, w2h);
    gather_trg<<<(BB * (TT - 1) * (EE / 4) + 255) / 256, 256, 0, s2>>>(trg, dec_embed, p_demb);
    gemm_k<0,0><<<dim3(G3 / 64, (BB * (TT - 1) + 63) / 64), 256, 0, s2>>>(
        p_demb, Wi_d, bi_d, p_gid, BB * (TT - 1), G3, EE);
    cudaEventRecord(evGid, s2);

    // ---- main: encoder recurrence ----
    cudaStreamWaitEvent(0, evPack, 0);
    cudaStreamWaitEvent(0, evGib, 0);
    enc_persist<<<128, 256, RSMEM2>>>(p_whTe, bh_f, bh_b, src_lens, p_gif, p_gib, p_henc, p_wr);
    cudaEventRecord(evEnc, 0);
    float* p_sent = p_henc;

    // ---- main: K + e2d; s2: V (concurrent) ----
    gemm_k<0,0><<<dim3(KKQ / 64, (BB * SS) / 64), 256>>>(p_wr, Wk, bk, p_K, BB * SS, KKQ, 2 * HH);
    gemm_k<1,0><<<dim3(DD / 64, 1), 256>>>(p_sent, W_e2d, b_e2d, p_hdec, BB, DD, 2 * HH);
    cudaStreamWaitEvent(s2, evEnc, 0);
    gemm_k<0,0><<<dim3(DD / 64, (BB * SS) / 64), 256, 0, s2>>>(p_wr, Wv, bv, p_V, BB * SS, DD, 2 * HH);
    cudaEventRecord(evV, s2);

    cudaStreamWaitEvent(0, evGid, 0);
    cudaStreamWaitEvent(0, evV, 0);

    // ---- 4-way decoder/head pipeline (16/16/16/15 chunks) ----
    for (int c = 0; c < 4; c++) {
        int t0 = c * 16;
        int t1 = (c == 3) ? (TT - 1) : (c * 16 + 16);
        dec_persist<<<64, 256, RSMEM2>>>(p_whTd, bh_d, p_gid, Wq, bq, p_K, p_V,
                                         p_hdec, p_hid, p_hgru, t0, t1, 4 + c);
        int m0 = c * 512;
        int mrows = (c == 3) ? (MROWS - m0) : 512;
        if (c < 3) {
            cudaEventRecord(evD[c], 0);
            cudaStreamWaitEvent(s2, evD[c], 0);
            gemm_k<1,1><<<dim3(DD / 64, 8), 256, 0, s2>>>(
                p_hid + (size_t)m0 * DD, W1, b1, xh + (size_t)m0 * DD, mrows, DD, DD);
            head_mma<<<dim3(4, VOC / 128), 256, 0, s2>>>(xh, w2h, b2, out, c * 4);
            if (c == 2) cudaEventRecord(evJoin, s2);
        } else {
            gemm_k<1,1><<<dim3(DD / 64, 8), 256>>>(
                p_hid + (size_t)m0 * DD, W1, b1, xh + (size_t)m0 * DD, mrows, DD, DD);
            head_mma<<<dim3(4, VOC / 128), 256>>>(xh, w2h, b2, out, 12);
        }
    }

    // join s2
    cudaStreamWaitEvent(0, evJoin, 0);
}

// round 17
// speedup vs baseline: 1.1723x; 1.0116x over previous
#include <cuda_runtime.h>
#include <cuda_fp16.h>
#include <cstdint>
#include <math.h>

#define BB   32
#define SS   64
#define TT   64
#define EE   256
#define HH   512
#define DD   512
#define KKQ  64
#define VOC  32000
#define G3   1536
#define MROWS (BB*(TT-1))   // 2016

#define NF_EMB   (BB*SS*EE)
#define NF_GI    (BB*SS*G3)
#define NF_WR    (BB*SS*2*HH)
#define NF_HENC  (2*BB*2*HH)
#define NF_K     (BB*SS*KKQ)
#define NF_V     (BB*SS*DD)
#define NF_DEMB  (BB*(TT-1)*EE)
#define NF_GID   (BB*(TT-1)*G3)
#define NF_HDEC  (BB*DD)
#define NF_HID   (BB*(TT-1)*DD)
#define NF_WHTE  (2*512*1536)
#define NF_WHTD  (512*1536)
#define NF_HGRU  (BB*DD)

#define NF_TOTAL (NF_EMB + 2*NF_GI + NF_WR + NF_HENC + NF_K + NF_V + NF_DEMB + NF_GID + \
                  NF_HDEC + NF_HID + NF_WHTE + NF_WHTD + NF_HGRU)

__device__ float g_scr[NF_TOTAL];
__device__ __half g_xh[MROWS * DD];
__device__ __half g_w2h[VOC * DD];
__device__ unsigned g_bars[12];   // 0..3 enc (dir,bg) groups; 4..8 dec chunks

__device__ __forceinline__ float sigm(float x) { return 1.0f / (1.0f + expf(-x)); }
__device__ __forceinline__ float gelu_f(float x) { return 0.5f * x * (1.0f + erff(x * 0.7071067811865475f)); }

__device__ __forceinline__ float ldcg1(const float* p) {
    float v; asm volatile("ld.global.cg.f32 %0, [%1];" : "=f"(v) : "l"(p)); return v;
}
__device__ __forceinline__ float4 ldcg4(const float* p) {
    float4 v;
    asm volatile("ld.global.cg.v4.f32 {%0,%1,%2,%3}, [%4];"
                 : "=f"(v.x), "=f"(v.y), "=f"(v.z), "=f"(v.w) : "l"(p));
    return v;
}

__device__ __forceinline__ void ffma2(unsigned long long& d,
                                      unsigned long long a, unsigned long long b) {
    asm("fma.rn.f32x2 %0, %1, %2, %0;" : "+l"(d) : "l"(a), "l"(b));
}
__device__ __forceinline__ unsigned long long splat2(float a) {
    unsigned long long r;
    asm("mov.b64 %0, {%1, %1};" : "=l"(r) : "f"(a));
    return r;
}
__device__ __forceinline__ float hsum2(unsigned long long v) {
    float lo = __uint_as_float((unsigned)(v & 0xffffffffull));
    float hi = __uint_as_float((unsigned)(v >> 32));
    return lo + hi;
}
__device__ __forceinline__ float lane0(unsigned long long v) {
    return __uint_as_float((unsigned)(v & 0xffffffffull));
}
__device__ __forceinline__ float lane1(unsigned long long v) {
    return __uint_as_float((unsigned)(v >> 32));
}

// software barrier: release/acquire semantics (grid.sync pattern)
__device__ __forceinline__ void gsync(unsigned* bar, unsigned& epoch, unsigned nb) {
    __syncthreads();
    if (threadIdx.x == 0) {
        epoch += nb;
        asm volatile("red.release.gpu.global.add.u32 [%0], %1;"
                     :: "l"(bar), "r"(1u) : "memory");
        unsigned v;
        do {
            asm volatile("ld.acquire.gpu.global.u32 %0, [%1];"
                         : "=r"(v) : "l"(bar) : "memory");
            if (v >= epoch) break;
            __nanosleep(32);
        } while (true);
    }
    __syncthreads();
}

// ---------------- init ----------------
__global__ void init_zero(float* __restrict__ out, float* __restrict__ henc) {
    int i = blockIdx.x * blockDim.x + threadIdx.x;
    if (i < 12) g_bars[i] = 0;
    if (i < BB * VOC) {
        int b = i / VOC;
        out[(size_t)b * TT * VOC + (i % VOC)] = 0.0f;
    }
    if (i < NF_HENC) henc[i] = 0.0f;
}

// ---------------- embedding gathers ----------------
__global__ void gather_src(const int* __restrict__ src, const float* __restrict__ tab,
                           float* __restrict__ emb) {
    int i = blockIdx.x * blockDim.x + threadIdx.x;
    if (i >= BB * SS * (EE / 4)) return;
    int row = i / (EE / 4);
    int c   = i % (EE / 4);
    ((float4*)emb)[row * (EE / 4) + c] =
        ((const float4*)tab)[(size_t)src[row] * (EE / 4) + c];
}

__global__ void gather_trg(const int* __restrict__ trg, const float* __restrict__ tab,
                           float* __restrict__ demb) {
    int i = blockIdx.x * blockDim.x + threadIdx.x;
    if (i >= BB * (TT - 1) * (EE / 4)) return;
    int m = i / (EE / 4);
    int c = i % (EE / 4);
    int t = m / BB, b = m % BB;
    int tok = trg[b * TT + t];
    ((float4*)demb)[m * (EE / 4) + c] =
        ((const float4*)tab)[(size_t)tok * (EE / 4) + c];
}

// ---------------- transpose-pack recurrent weights: [dir][j][gate][k] ----------------
__global__ void pack_whT(const float* __restrict__ Wh_f, const float* __restrict__ Wh_b,
                         const float* __restrict__ Wh_d,
                         float* __restrict__ whTe, float* __restrict__ whTd) {
    int idx = blockIdx.x * blockDim.x + threadIdx.x;
    if (idx >= 512 * 512) return;
    int k = idx >> 9, j = idx & 511;
#pragma unroll
    for (int g = 0; g < 3; g++) {
        whTe[(size_t)(j * 3 + g) * 512 + k] = Wh_f[k * G3 + g * 512 + j];
        whTe[(size_t)512 * 1536 + (j * 3 + g) * 512 + k] = Wh_b[k * G3 + g * 512 + j];
        whTd[(size_t)(j * 3 + g) * 512 + k] = Wh_d[k * G3 + g * 512 + j];
    }
}

// ---------------- generic fp32 GEMM (f32x2 inner loop) ----------------
template<int GELU, int OUT16>
__global__ void gemm_k(const float* __restrict__ A, const float* __restrict__ Bm,
                       const float* __restrict__ bias, void* __restrict__ Cv,
                       int M, int N, int K) {
    __shared__ float As[16][68];
    __shared__ float Bs[16][68];
    int tid = threadIdx.x;
    int m0 = blockIdx.y * 64, n0 = blockIdx.x * 64;
    int tx = tid & 15, ty = tid >> 4;

    unsigned long long acc2[4][2];
#pragma unroll
    for (int i = 0; i < 4; i++) { acc2[i][0] = 0ull; acc2[i][1] = 0ull; }

    int lam = tid >> 2;
    int lak = (tid & 3) * 4;
    int lbk = tid >> 4;
    int lbn = (tid & 15) * 4;

    for (int k0 = 0; k0 < K; k0 += 16) {
        float4 av = (m0 + lam < M)
            ? *(const float4*)&A[(size_t)(m0 + lam) * K + k0 + lak]
            : make_float4(0.f, 0.f, 0.f, 0.f);
        float4 bv = *(const float4*)&Bm[(size_t)(k0 + lbk) * N + n0 + lbn];
        __syncthreads();
        As[lak + 0][lam] = av.x;
        As[lak + 1][lam] = av.y;
        As[lak + 2][lam] = av.z;
        As[lak + 3][lam] = av.w;
        *(float4*)&Bs[lbk][lbn] = bv;
        __syncthreads();
#pragma unroll
        for (int kk = 0; kk < 16; kk++) {
            float4 a4 = *(const float4*)&As[kk][ty * 4];
            unsigned long long b0 = *(const unsigned long long*)&Bs[kk][tx * 4];
            unsigned long long b1 = *(const unsigned long long*)&Bs[kk][tx * 4 + 2];
            unsigned long long s0 = splat2(a4.x);
            unsigned long long s1 = splat2(a4.y);
            unsigned long long s2 = splat2(a4.z);
            unsigned long long s3 = splat2(a4.w);
            ffma2(acc2[0][0], s0, b0); ffma2(acc2[0][1], s0, b1);
            ffma2(acc2[1][0], s1, b0); ffma2(acc2[1][1], s1, b1);
            ffma2(acc2[2][0], s2, b0); ffma2(acc2[2][1], s2, b1);
            ffma2(acc2[3][0], s3, b0); ffma2(acc2[3][1], s3, b1);
        }
    }

#pragma unroll
    for (int i = 0; i < 4; i++) {
        int m = m0 + ty * 4 + i;
        if (m >= M) continue;
        float vj[4] = { lane0(acc2[i][0]), lane1(acc2[i][0]),
                        lane0(acc2[i][1]), lane1(acc2[i][1]) };
#pragma unroll
        for (int j = 0; j < 4; j++) {
            int n = n0 + tx * 4 + j;
            float v = vj[j] + bias[n];
            if (GELU) v = gelu_f(v);
            if (OUT16) ((__half*)Cv)[(size_t)m * N + n] = __float2half(v);
            else       ((float*)Cv)[(size_t)m * N + n] = v;
        }
    }
}

// ===== recurrence smem layout =====
#define WP2   1538
#define HP2   516
#define OFF_H   (16 * WP2)
#define OFF_P   (16 * WP2 + 16 * HP2)
#define RSMEM2  ((16 * WP2 + 16 * HP2 + 16 * 3 * 16 * 16) * 4)   // 180608 B

__device__ __forceinline__ void fill_wslab(float* ws, const float* wsrc, int tid) {
#pragma unroll
    for (int u = 0; u < 24; u++) {
        int idx4 = u * 256 + tid;
        int jl = idx4 / 384;
        int off = (idx4 - jl * 384) * 4;
        float4 v = *(const float4*)&wsrc[(size_t)jl * 1536 + off];
        float* d = &ws[jl * WP2 + off];
        *(float2*)d = make_float2(v.x, v.y);
        *(float2*)(d + 2) = make_float2(v.z, v.w);
    }
}

__device__ __forceinline__ void gru_core(const float* ws, const float* hsf,
                                         float* part, int tx, int ty) {
    unsigned long long acc[16][3];
#pragma unroll
    for (int b = 0; b < 16; b++)
#pragma unroll
        for (int g = 0; g < 3; g++) acc[b][g] = 0ull;

    const float* wr_p = ws + tx * WP2 + ty * 32;
    const float* wz_p = wr_p + 512;
    const float* wn_p = wr_p + 1024;
    const float* h_p  = hsf + ty * 32;

#pragma unroll
    for (int kk2 = 0; kk2 < 16; kk2++) {
        unsigned long long wr = *(const unsigned long long*)(wr_p + kk2 * 2);
        unsigned long long wz = *(const unsigned long long*)(wz_p + kk2 * 2);
        unsigned long long wn = *(const unsigned long long*)(wn_p + kk2 * 2);
#pragma unroll
        for (int b = 0; b < 16; b++) {
            unsigned long long h2 = *(const unsigned long long*)(h_p + b * HP2 + kk2 * 2);
            ffma2(acc[b][0], h2, wr);
            ffma2(acc[b][1], h2, wz);
            ffma2(acc[b][2], h2, wn);
        }
    }
#pragma unroll
    for (int b = 0; b < 16; b++)
#pragma unroll
        for (int g = 0; g < 3; g++)
            part[((b * 3 + g) * 16 + ty) * 16 + tx] = hsum2(acc[b][g]);
}

// ================= persistent encoder: 4 independent (dir,bg) barrier groups =================
__global__ void __launch_bounds__(256, 1)
enc_persist(const float* __restrict__ whTe,
            const float* __restrict__ bh_f, const float* __restrict__ bh_b,
            const int* __restrict__ src_lens,
            const float* __restrict__ gi_f, const float* __restrict__ gi_b,
            float* __restrict__ henc, float* __restrict__ wr_out) {
    extern __shared__ float smem[];
    float* ws   = smem;
    float* hsf  = smem + OFF_H;
    float* part = smem + OFF_P;

    int cta = blockIdx.x;
    int dir = cta & 1, bg = (cta >> 1) & 1, jt = cta >> 2;
    unsigned* bar = &g_bars[cta & 3];
    int tid = threadIdx.x;
    int tx = tid & 15, ty = tid >> 4;
    const float* bh = dir ? bh_b : bh_f;
    const float* gi = dir ? gi_b : gi_f;

    fill_wslab(ws, whTe + (size_t)dir * 512 * 1536 + (size_t)jt * 16 * 1536, tid);

    int j_g = jt * 16 + tx;
    int b_g = bg * 16 + ty;
    float br = bh[j_g], bz = bh[512 + j_g], bn = bh[1024 + j_g];
    int len = max(src_lens[b_g], 1);
    unsigned epoch = 0;
    __syncthreads();

    for (int step = 0; step < SS; step++) {
        int t = dir ? (SS - 1 - step) : step;
        int p = step & 1;
        const float* hin = henc + p * (BB * 1024);
        float* hout = henc + (p ^ 1) * (BB * 1024);

#pragma unroll
        for (int u = 0; u < 8; u++) {
            int idx = u * 256 + tid;
            int bl = idx >> 7, kq = idx & 127;
            float4 h4 = ldcg4(&hin[(bg * 16 + bl) * 1024 + dir * 512 + kq * 4]);
            *(float4*)&hsf[bl * HP2 + kq * 4] = h4;
        }
        __syncthreads();

        gru_core(ws, hsf, part, tx, ty);
        __syncthreads();

        {
            float sr = 0.f, sz = 0.f, sn = 0.f;
#pragma unroll
            for (int s = 0; s < 16; s++) {
                sr += part[((ty * 3 + 0) * 16 + s) * 16 + tx];
                sz += part[((ty * 3 + 1) * 16 + s) * 16 + tx];
                sn += part[((ty * 3 + 2) * 16 + s) * 16 + tx];
            }
            size_t row = (size_t)(b_g * SS + t);
            float gir = gi[row * G3 + j_g];
            float giz = gi[row * G3 + 512 + j_g];
            float gin = gi[row * G3 + 1024 + j_g];
            float hold = hsf[ty * HP2 + j_g];
            float r = sigm(gir + sr + br);
            float z = sigm(giz + sz + bz);
            float n = tanhf(gin + r * (sn + bn));
            float hnew = (1.0f - z) * n + z * hold;
            bool valid = t < len;
            hout[b_g * 1024 + dir * 512 + j_g] = valid ? hnew : hold;
            wr_out[row * 1024 + dir * 512 + j_g] = valid ? hnew : 0.0f;
        }
        gsync(bar, epoch, 32);
    }
}

// ================= persistent decoder (t-range chunk, own barrier counter) =================
// attention split over all 64 CTAs: 2 per batch (ba = cta>>1, d-half = cta&1)
__global__ void __launch_bounds__(256, 1)
dec_persist(const float* __restrict__ whTd, const float* __restrict__ bh,
            const float* __restrict__ gi,
            const float* __restrict__ Wq, const float* __restrict__ bq,
            const float* __restrict__ Kmat, const float* __restrict__ Vmat,
            float* __restrict__ hdec, float* __restrict__ hid_all,
            float* __restrict__ hgru, int t0, int t1, int bar_idx) {
    extern __shared__ float smem[];
    float* ws   = smem;
    float* hsf  = smem + OFF_H;
    float* part = smem + OFF_P;
    __shared__ float hsh[DD];
    __shared__ float qsh[KKQ];
    __shared__ float ssh[SS];
    __shared__ float red[256];

    int cta = blockIdx.x;
    int bg = cta & 1, jt = cta >> 1;
    int tid = threadIdx.x;
    int tx = tid & 15, ty = tid >> 4;
    unsigned* bar = &g_bars[bar_idx];
    int ba = cta >> 1;            // attention batch (0..31)
    int dh = (cta & 1) * 256;     // attention d-half offset

    fill_wslab(ws, whTd + (size_t)jt * 16 * 1536, tid);

    int j_g = jt * 16 + tx;
    int b_g = bg * 16 + ty;
    float br = bh[j_g], bz = bh[512 + j_g], bn = bh[1024 + j_g];
    unsigned epoch = 0;
    __syncthreads();

    for (int t = t0; t < t1; t++) {
#pragma unroll
        for (int u = 0; u < 4; u++) {
            int idx = u * 256 + tid;
            int bl = idx >> 6, kq = idx & 63;
            float4 h4 = ldcg4(&hdec[(bg * 16 + bl) * 512 + kq * 8]);
            float4 h4b = ldcg4(&hdec[(bg * 16 + bl) * 512 + kq * 8 + 4]);
            *(float4*)&hsf[bl * HP2 + kq * 8] = h4;
            *(float4*)&hsf[bl * HP2 + kq * 8 + 4] = h4b;
        }
        __syncthreads();

        gru_core(ws, hsf, part, tx, ty);
        __syncthreads();

        {
            float sr = 0.f, sz = 0.f, sn = 0.f;
#pragma unroll
            for (int s = 0; s < 16; s++) {
                sr += part[((ty * 3 + 0) * 16 + s) * 16 + tx];
                sz += part[((ty * 3 + 1) * 16 + s) * 16 + tx];
                sn += part[((ty * 3 + 2) * 16 + s) * 16 + tx];
            }
            size_t row = (size_t)(t * BB + b_g);
            float gir = gi[row * G3 + j_g];
            float giz = gi[row * G3 + 512 + j_g];
            float gin = gi[row * G3 + 1024 + j_g];
            float hold = hsf[ty * HP2 + j_g];
            float r = sigm(gir + sr + br);
            float z = sigm(giz + sz + bz);
            float n = tanhf(gin + r * (sn + bn));
            hgru[b_g * 512 + j_g] = (1.0f - z) * n + z * hold;
        }
        gsync(bar, epoch, gridDim.x);

        // attention: 2 CTAs per batch; softmax recomputed redundantly (deterministic)
        {
            size_t rowa = (size_t)(t * BB + ba);
            for (int i = tid; i < DD; i += 256) hsh[i] = ldcg1(&hgru[ba * 512 + i]);
            __syncthreads();
            {
                int jq = tid & 63, prt = tid >> 6;
                float acc = 0.f;
                int kb = prt * 128;
                for (int k = kb; k < kb + 128; k++) acc = fmaf(hsh[k], Wq[k * KKQ + jq], acc);
                red[tid] = acc;
            }
            __syncthreads();
            if (tid < KKQ) {
                float q = red[tid] + red[tid + 64] + red[tid + 128] + red[tid + 192] + bq[tid];
                qsh[tid] = q * 0.125f;
            }
            __syncthreads();
            if (tid < SS) {
                const float* Kp = Kmat + (size_t)(ba * SS + tid) * KKQ;
                float sc = 0.f;
                for (int k = 0; k < KKQ; k++) sc = fmaf(qsh[k], Kp[k], sc);
                ssh[tid] = sc;
            }
            __syncthreads();
            if (tid == 0) {
                float m = ssh[0];
                for (int s = 1; s < SS; s++) m = fmaxf(m, ssh[s]);
                float sum = 0.f;
                for (int s = 0; s < SS; s++) { float e = expf(ssh[s] - m); ssh[s] = e; sum += e; }
                red[0] = 1.0f / sum;
            }
            __syncthreads();
            float inv = red[0];
            __syncthreads();
            if (tid < SS) ssh[tid] *= inv;
            __syncthreads();
            {
                int d0 = dh + tid;   // this CTA's 256-wide d-half, 1 elem/thread
                float a = 0.f;
                for (int s = 0; s < SS; s++)
                    a = fmaf(ssh[s], Vmat[(size_t)(ba * SS + s) * DD + d0], a);
                float hid = hsh[d0] + a;
                hdec[ba * 512 + d0] = hid;
                hid_all[rowa * 512 + d0] = hid;
            }
        }
        gsync(bar, epoch, gridDim.x);
    }
}

// transpose W2 [K=512, N=32000] fp32 -> W2h [N, K] fp16
__global__ void transpose_w2(const float* __restrict__ W2, __half* __restrict__ W2h) {
    __shared__ float ts[32][33];
    int n0 = blockIdx.x * 32;
    int k0 = blockIdx.y * 32;
    int tx = threadIdx.x, ty = threadIdx.y;
#pragma unroll
    for (int j = 0; j < 4; j++)
        ts[ty + j * 8][tx] = W2[(size_t)(k0 + ty + j * 8) * VOC + n0 + tx];
    __syncthreads();
#pragma unroll
    for (int j = 0; j < 4; j++) {
        int n = n0 + ty + j * 8;
        int k = k0 + tx;
        W2h[(size_t)n * DD + k] = __float2half(ts[tx][ty + j * 8]);
    }
}

// ================= HMMA fp16 head GEMM (m-tile offset) =================
#define HPITCH 72

__device__ __forceinline__ uint32_t smem_u32(const void* p) {
    uint32_t a;
    asm("{ .reg .u64 t; cvta.to.shared.u64 t, %1; cvt.u32.u64 %0, t; }" : "=r"(a) : "l"(p));
    return a;
}
__device__ __forceinline__ void ldmatrix_x4(uint32_t* r, uint32_t addr) {
    asm volatile("ldmatrix.sync.aligned.m8n8.x4.shared.b16 {%0,%1,%2,%3}, [%4];"
                 : "=r"(r[0]), "=r"(r[1]), "=r"(r[2]), "=r"(r[3]) : "r"(addr));
}
__device__ __forceinline__ void ldmatrix_x2(uint32_t* r, uint32_t addr) {
    asm volatile("ldmatrix.sync.aligned.m8n8.x2.shared.b16 {%0,%1}, [%2];"
                 : "=r"(r[0]), "=r"(r[1]) : "r"(addr));
}
__device__ __forceinline__ void mma16816(float* c, const uint32_t* a, const uint32_t* b) {
    asm volatile(
        "mma.sync.aligned.m16n8k16.row.col.f32.f16.f16.f32 "
        "{%0,%1,%2,%3}, {%4,%5,%6,%7}, {%8,%9}, {%0,%1,%2,%3};"
        : "+f"(c[0]), "+f"(c[1]), "+f"(c[2]), "+f"(c[3])
        : "r"(a[0]), "r"(a[1]), "r"(a[2]), "r"(a[3]), "r"(b[0]), "r"(b[1]));
}

__global__ void __launch_bounds__(256, 2)
head_mma(const __half* __restrict__ Xh, const __half* __restrict__ W2h,
         const float* __restrict__ b2, float* __restrict__ out, int moff) {
    __shared__ __half As[128 * HPITCH];
    __shared__ __half Bs[128 * HPITCH];

    int tid = threadIdx.x;
    int wid = tid >> 5, lane = tid & 31;
    int m0 = (blockIdx.x + moff) * 128;
    int n0 = blockIdx.y * 128;
    int wm = (wid >> 2) * 64;
    int wn = (wid & 3) * 32;

    float c[4][4][4];
#pragma unroll
    for (int mi = 0; mi < 4; mi++)
#pragma unroll
        for (int ni = 0; ni < 4; ni++)
#pragma unroll
            for (int q = 0; q < 4; q++) c[mi][ni][q] = 0.0f;

    uint32_t as_base = smem_u32(As);
    uint32_t bs_base = smem_u32(Bs);

    for (int kc = 0; kc < 8; kc++) {
        int k0 = kc * 64;
        __syncthreads();
#pragma unroll
        for (int it = 0; it < 4; it++) {
            int idx = it * 256 + tid;
            int row = idx >> 3;
            int col = (idx & 7) * 8;
            uint4 va = (m0 + row < MROWS)
                ? *(const uint4*)(Xh + (size_t)(m0 + row) * DD + k0 + col)
                : make_uint4(0, 0, 0, 0);
            *(uint4*)(As + row * HPITCH + col) = va;
            uint4 vb = *(const uint4*)(W2h + (size_t)(n0 + row) * DD + k0 + col);
            *(uint4*)(Bs + row * HPITCH + col) = vb;
        }
        __syncthreads();

#pragma unroll
        for (int k16 = 0; k16 < 4; k16++) {
            uint32_t afrag[4][4], bfrag[4][2];
#pragma unroll
            for (int mi = 0; mi < 4; mi++) {
                int r = wm + mi * 16 + (lane & 15);
                int cl = k16 * 16 + ((lane >> 4) * 8);
                ldmatrix_x4(afrag[mi], as_base + (uint32_t)(r * HPITCH + cl) * 2);
            }
#pragma unroll
            for (int ni = 0; ni < 4; ni++) {
                int r = wn + ni * 8 + (lane & 7);
                int cl = k16 * 16 + (((lane >> 3) & 1) * 8);
                ldmatrix_x2(bfrag[ni], bs_base + (uint32_t)(r * HPITCH + cl) * 2);
            }
#pragma unroll
            for (int mi = 0; mi < 4; mi++)
#pragma unroll
                for (int ni = 0; ni < 4; ni++)
                    mma16816(c[mi][ni], afrag[mi], bfrag[ni]);
        }
    }

    int rbase = lane >> 2;
    int cbase = (lane & 3) * 2;
#pragma unroll
    for (int mi = 0; mi < 4; mi++) {
#pragma unroll
        for (int half2i = 0; half2i < 2; half2i++) {
            int m = m0 + wm + mi * 16 + rbase + half2i * 8;
            if (m >= MROWS) continue;
            int b = m & 31, t = m >> 5;
            float* orow = out + (size_t)(b * TT + t + 1) * VOC;
#pragma unroll
            for (int ni = 0; ni < 4; ni++) {
                int n = n0 + wn + ni * 8 + cbase;
                float2 v;
                v.x = c[mi][ni][half2i * 2 + 0] + b2[n];
                v.y = c[mi][ni][half2i * 2 + 1] + b2[n + 1];
                *(float2*)(orow + n) = v;
            }
        }
    }
}

// ================================ host ================================
extern "C" void kernel_launch(void* const* d_in, const int* in_sizes, int n_in,
                              void* d_out, int out_size) {
    const int*   src       = (const int*)  d_in[0];
    const int*   trg       = (const int*)  d_in[1];
    const int*   src_lens  = (const int*)  d_in[2];
    const float* enc_embed = (const float*)d_in[3];
    const float* Wi_f      = (const float*)d_in[4];
    const float* Wh_f      = (const float*)d_in[5];
    const float* bi_f      = (const float*)d_in[6];
    const float* bh_f      = (const float*)d_in[7];
    const float* Wi_b      = (const float*)d_in[8];
    const float* Wh_b      = (const float*)d_in[9];
    const float* bi_b      = (const float*)d_in[10];
    const float* bh_b      = (const float*)d_in[11];
    const float* W_e2d     = (const float*)d_in[12];
    const float* b_e2d     = (const float*)d_in[13];
    const float* dec_embed = (const float*)d_in[14];
    const float* Wi_d      = (const float*)d_in[15];
    const float* Wh_d      = (const float*)d_in[16];
    const float* bi_d      = (const float*)d_in[17];
    const float* bh_d      = (const float*)d_in[18];
    const float* Wq        = (const float*)d_in[19];
    const float* bq        = (const float*)d_in[20];
    const float* Wk        = (const float*)d_in[21];
    const float* bk        = (const float*)d_in[22];
    const float* Wv        = (const float*)d_in[23];
    const float* bv        = (const float*)d_in[24];
    const float* W1        = (const float*)d_in[25];
    const float* b1        = (const float*)d_in[26];
    const float* W2        = (const float*)d_in[27];
    const float* b2        = (const float*)d_in[28];
    float* out = (float*)d_out;

    float* scr = nullptr;
    cudaGetSymbolAddress((void**)&scr, g_scr);
    __half* xh = nullptr;
    cudaGetSymbolAddress((void**)&xh, g_xh);
    __half* w2h = nullptr;
    cudaGetSymbolAddress((void**)&w2h, g_w2h);

    float* p_emb  = scr;
    float* p_gif  = p_emb  + NF_EMB;
    float* p_gib  = p_gif  + NF_GI;
    float* p_wr   = p_gib  + NF_GI;
    float* p_henc = p_wr   + NF_WR;
    float* p_K    = p_henc + NF_HENC;
    float* p_V    = p_K    + NF_K;
    float* p_demb = p_V    + NF_V;
    float* p_gid  = p_demb + NF_DEMB;
    float* p_hdec = p_gid  + NF_GID;
    float* p_hid  = p_hdec + NF_HDEC;
    float* p_whTe = p_hid  + NF_HID;
    float* p_whTd = p_whTe + NF_WHTE;
    float* p_hgru = p_whTd + NF_WHTD;

    static cudaStream_t s2;
    static cudaEvent_t evFork, evEmb, evPack, evGib, evGid, evEnc, evV, evD[4], evJoin;
    static int once = 0;
    if (!once) {
        cudaFuncSetAttribute(enc_persist, cudaFuncAttributeMaxDynamicSharedMemorySize, RSMEM2);
        cudaFuncSetAttribute(dec_persist, cudaFuncAttributeMaxDynamicSharedMemorySize, RSMEM2);
        cudaStreamCreateWithFlags(&s2, cudaStreamNonBlocking);
        cudaEventCreateWithFlags(&evFork, cudaEventDisableTiming);
        cudaEventCreateWithFlags(&evEmb,  cudaEventDisableTiming);
        cudaEventCreateWithFlags(&evPack, cudaEventDisableTiming);
        cudaEventCreateWithFlags(&evGib,  cudaEventDisableTiming);
        cudaEventCreateWithFlags(&evGid,  cudaEventDisableTiming);
        cudaEventCreateWithFlags(&evEnc,  cudaEventDisableTiming);
        cudaEventCreateWithFlags(&evV,    cudaEventDisableTiming);
        for (int i = 0; i < 4; i++) cudaEventCreateWithFlags(&evD[i], cudaEventDisableTiming);
        cudaEventCreateWithFlags(&evJoin, cudaEventDisableTiming);
        once = 1;
    }

    // 0) init on main stream, then fork s2
    init_zero<<<(BB * VOC + 255) / 256, 256>>>(out, p_henc);
    cudaEventRecord(evFork, 0);
    cudaStreamWaitEvent(s2, evFork, 0);

    // ---- main: encoder embeddings + gi_f ----
    gather_src<<<(BB * SS * (EE / 4) + 255) / 256, 256>>>(src, enc_embed, p_emb);
    cudaEventRecord(evEmb, 0);
    gemm_k<0,0><<<dim3(G3 / 64, (BB * SS) / 64), 256>>>(p_emb, Wi_f, bi_f, p_gif, BB * SS, G3, EE);

    // ---- s2: pack weights early, then gi_b (concurrent with gi_f), then deferred prep ----
    pack_whT<<<(512 * 512 + 255) / 256, 256, 0, s2>>>(Wh_f, Wh_b, Wh_d, p_whTe, p_whTd);
    cudaEventRecord(evPack, s2);
    cudaStreamWaitEvent(s2, evEmb, 0);
    gemm_k<0,0><<<dim3(G3 / 64, (BB * SS) / 64), 256, 0, s2>>>(p_emb, Wi_b, bi_b, p_gib, BB * SS, G3, EE);
    cudaEventRecord(evGib, s2);
    transpose_w2<<<dim3(VOC / 32, DD / 32), dim3(32, 8), 0, s2>>>(W2, w2h);
    gather_trg<<<(BB * (TT - 1) * (EE / 4) + 255) / 256, 256, 0, s2>>>(trg, dec_embed, p_demb);
    gemm_k<0,0><<<dim3(G3 / 64, (BB * (TT - 1) + 63) / 64), 256, 0, s2>>>(
        p_demb, Wi_d, bi_d, p_gid, BB * (TT - 1), G3, EE);
    cudaEventRecord(evGid, s2);

    // ---- main: encoder recurrence ----
    cudaStreamWaitEvent(0, evPack, 0);
    cudaStreamWaitEvent(0, evGib, 0);
    enc_persist<<<128, 256, RSMEM2>>>(p_whTe, bh_f, bh_b, src_lens, p_gif, p_gib, p_henc, p_wr);
    cudaEventRecord(evEnc, 0);
    float* p_sent = p_henc;

    // ---- main: K + e2d; s2: V (concurrent) ----
    gemm_k<0,0><<<dim3(KKQ / 64, (BB * SS) / 64), 256>>>(p_wr, Wk, bk, p_K, BB * SS, KKQ, 2 * HH);
    gemm_k<1,0><<<dim3(DD / 64, 1), 256>>>(p_sent, W_e2d, b_e2d, p_hdec, BB, DD, 2 * HH);
    cudaStreamWaitEvent(s2, evEnc, 0);
    gemm_k<0,0><<<dim3(DD / 64, (BB * SS) / 64), 256, 0, s2>>>(p_wr, Wv, bv, p_V, BB * SS, DD, 2 * HH);
    cudaEventRecord(evV, s2);

    cudaStreamWaitEvent(0, evGid, 0);
    cudaStreamWaitEvent(0, evV, 0);

    // ---- 5-way decoder/head pipeline: chunks 16/16/16/8/7, tail-light ----
    // boundaries keep hid-row chunks 128-aligned: m = 0/512/1024/1536/1792/2016
    const int tsplit[6] = {0, 16, 32, 48, 56, TT - 1};
    for (int c = 0; c < 5; c++) {
        int t0 = tsplit[c], t1 = tsplit[c + 1];
        dec_persist<<<64, 256, RSMEM2>>>(p_whTd, bh_d, p_gid, Wq, bq, p_K, p_V,
                                         p_hdec, p_hid, p_hgru, t0, t1, 4 + c);
        int m0 = t0 * BB;
        int mrows = (c == 4) ? (MROWS - m0) : (t1 - t0) * BB;   // 512,512,512,256,224
        int tile0 = m0 / 128;                                   // 0,4,8,12,14
        int ntiles = (c == 4) ? (16 - tile0) : (mrows / 128);   // 4,4,4,2,2
        if (c < 4) {
            cudaEventRecord(evD[c], 0);
            cudaStreamWaitEvent(s2, evD[c], 0);
            gemm_k<1,1><<<dim3(DD / 64, (mrows + 63) / 64), 256, 0, s2>>>(
                p_hid + (size_t)m0 * DD, W1, b1, xh + (size_t)m0 * DD, mrows, DD, DD);
            head_mma<<<dim3(ntiles, VOC / 128), 256, 0, s2>>>(xh, w2h, b2, out, tile0);
            if (c == 3) cudaEventRecord(evJoin, s2);
        } else {
            gemm_k<1,1><<<dim3(DD / 64, (mrows + 63) / 64), 256>>>(
                p_hid + (size_t)m0 * DD, W1, b1, xh + (size_t)m0 * DD, mrows, DD, DD);
            head_mma<<<dim3(ntiles, VOC / 128), 256>>>(xh, w2h, b2, out, tile0);
        }
    }

    // join s2
    cudaStreamWaitEvent(0, evJoin, 0);
}